// round 14
// baseline (speedup 1.0000x reference)
#include <cuda_runtime.h>
#include <cuda_bf16.h>
#include <cstdint>

#define N_NODES 100000
#define N_EDGES 1600000
#define N_GRAPHS 256
#define F_IN 128
#define HDIM 256
#define EPS 1e-5f

#define SB 512
#define NB ((N_NODES + SB - 1) / SB)   // 196

// ========================== PTX helpers (sm_80-class only) ===================
__device__ __forceinline__ uint32_t smem_to_u32(const void* p) {
    uint32_t a;
    asm("{ .reg .u64 t; cvta.to.shared.u64 t, %1; cvt.u32.u64 %0, t; }" : "=r"(a) : "l"(p));
    return a;
}
__device__ __forceinline__ void cp16(uint32_t d, const void* s) {
    asm volatile("cp.async.cg.shared.global [%0], [%1], 16;" :: "r"(d), "l"(s));
}
__device__ __forceinline__ void cp_commit() { asm volatile("cp.async.commit_group;" ::: "memory"); }
template <int N> __device__ __forceinline__ void cp_wait() {
    asm volatile("cp.async.wait_group %0;" :: "n"(N) : "memory");
}
__device__ __forceinline__ void ldm_x4(uint32_t* d, uint32_t addr) {
    asm volatile("ldmatrix.sync.aligned.m8n8.x4.shared.b16 {%0,%1,%2,%3}, [%4];"
                 : "=r"(d[0]), "=r"(d[1]), "=r"(d[2]), "=r"(d[3]) : "r"(addr));
}
__device__ __forceinline__ void ldm_x2(uint32_t* d, uint32_t addr) {
    asm volatile("ldmatrix.sync.aligned.m8n8.x2.shared.b16 {%0,%1}, [%2];"
                 : "=r"(d[0]), "=r"(d[1]) : "r"(addr));
}
__device__ __forceinline__ void mma_bf16(float* c, const uint32_t* a, const uint32_t* b) {
    asm volatile("mma.sync.aligned.m16n8k16.row.col.f32.bf16.bf16.f32 "
                 "{%0,%1,%2,%3}, {%4,%5,%6,%7}, {%8,%9}, {%0,%1,%2,%3};"
                 : "+f"(c[0]), "+f"(c[1]), "+f"(c[2]), "+f"(c[3])
                 : "r"(a[0]), "r"(a[1]), "r"(a[2]), "r"(a[3]), "r"(b[0]), "r"(b[1]));
}

// ============================ scratch (static) ================================
// NOTE: buffer set/sizes/order preserved from the champion build — layout matters
// (R8/R9 showed deleting g_hl cost ~240us). g_h2 stays declared fp32-sized; we
// store bf16 into its first half. g_btl stays allocated+written even though the
// main GEMMs no longer read it (residual GEMM still does).
__device__ __align__(256) float g_h2[(size_t)N_NODES * HDIM];
__device__ __align__(256) __nv_bfloat16 g_hh [(size_t)N_NODES * HDIM];
__device__ __align__(256) __nv_bfloat16 g_hl [(size_t)N_NODES * HDIM];
__device__ __align__(256) __nv_bfloat16 g_aggh[(size_t)N_NODES * HDIM];
__device__ __align__(256) __nv_bfloat16 g_xh[(size_t)N_NODES * F_IN];
__device__ __align__(256) __nv_bfloat16 g_bth[9][HDIM * HDIM];
__device__ __align__(256) __nv_bfloat16 g_btl[9][HDIM * HDIM];
__device__ int   g_deg[N_NODES];
__device__ float g_deginv[N_NODES];
__device__ int   g_rowptr[N_NODES + 1];
__device__ int   g_cursor[N_NODES];
__device__ int   g_csr[N_EDGES];
__device__ int   g_blksum[NB];
__device__ int   g_blkoff[NB];
__device__ float g_colsum[HDIM];
__device__ float g_colsumsq[HDIM];
__device__ float g_scale[HDIM];
__device__ float g_shift[HDIM];
__device__ float g_pool[N_GRAPHS * HDIM];
__device__ int   g_is64;

// =================== prologue: dtype detect + zero deg/cursor ================
__global__ void k_prep0(const int* __restrict__ ei32) {
    int i = blockIdx.x * 256 + threadIdx.x;
    if (i < N_NODES) { g_deg[i] = 0; g_cursor[i] = 0; }
    if (blockIdx.x == 0) {
        __shared__ int nz;
        if (threadIdx.x == 0) nz = 0;
        __syncthreads();
        int acc = 0;
#pragma unroll
        for (int q = 0; q < 4; q++) acc |= ei32[2 * (threadIdx.x * 4 + q) + 1];
        if (acc) atomicOr(&nz, 1);
        __syncthreads();
        if (threadIdx.x == 0) g_is64 = (nz == 0) ? 1 : 0;
    }
}
__device__ __forceinline__ long long load_idx(const void* p, long long i, int is64) {
    return is64 ? ((const long long*)p)[i] : (long long)((const int*)p)[i];
}
__global__ void k_degree(const void* __restrict__ ei, int* __restrict__ deg) {
    int e = blockIdx.x * blockDim.x + threadIdx.x;
    if (e >= N_EDGES) return;
    int dst = (int)load_idx(ei, (long long)N_EDGES + e, g_is64);
    atomicAdd(&deg[dst], 1);
}
__global__ void k_scan_partial(const int* __restrict__ deg, int* __restrict__ blksum) {
    __shared__ int sh[SB];
    int i = blockIdx.x * SB + threadIdx.x;
    sh[threadIdx.x] = (i < N_NODES) ? deg[i] : 0;
    __syncthreads();
    for (int o = SB / 2; o > 0; o >>= 1) {
        if (threadIdx.x < o) sh[threadIdx.x] += sh[threadIdx.x + o];
        __syncthreads();
    }
    if (threadIdx.x == 0) blksum[blockIdx.x] = sh[0];
}
__global__ void k_scan_blk(const int* __restrict__ blksum, int* __restrict__ blkoff,
                           int* __restrict__ rowptr) {
    if (threadIdx.x == 0) {
        int a = 0;
        for (int b = 0; b < NB; b++) { blkoff[b] = a; a += blksum[b]; }
        rowptr[N_NODES] = a;
    }
}
__global__ void k_scan_final(const int* __restrict__ deg, const int* __restrict__ blkoff,
                             int* __restrict__ rowptr, float* __restrict__ deginv) {
    __shared__ int sh[SB];
    int i = blockIdx.x * SB + threadIdx.x;
    int v = (i < N_NODES) ? deg[i] : 0;
    sh[threadIdx.x] = v;
    __syncthreads();
    for (int o = 1; o < SB; o <<= 1) {
        int t = (threadIdx.x >= o) ? sh[threadIdx.x - o] : 0;
        __syncthreads();
        sh[threadIdx.x] += t;
        __syncthreads();
    }
    if (i < N_NODES) {
        rowptr[i] = blkoff[blockIdx.x] + sh[threadIdx.x] - v;
        deginv[i] = 1.0f / (float)max(v, 1);
    }
}
__global__ void k_fillcsr(const void* __restrict__ ei, const int* __restrict__ rowptr,
                          int* __restrict__ cursor, int* __restrict__ csr) {
    int e = blockIdx.x * blockDim.x + threadIdx.x;
    if (e >= N_EDGES) return;
    int is64 = g_is64;
    int src = (int)load_idx(ei, e, is64);
    int dst = (int)load_idx(ei, (long long)N_EDGES + e, is64);
    int p = atomicAdd(&cursor[dst], 1);
    csr[rowptr[dst] + p] = src;
}

// ========== aggregation: CSR gather (16B vector loads) -> bf16 mean ==========
template <int F>
__global__ void __launch_bounds__(256) k_agg(
    const __nv_bfloat16* __restrict__ XH, const int* __restrict__ rowptr,
    const int* __restrict__ csr, const float* __restrict__ deginv,
    __nv_bfloat16* __restrict__ AH)
{
    if (blockIdx.x == 0) { g_colsum[threadIdx.x] = 0.f; g_colsumsq[threadIdx.x] = 0.f; }
    int node = (blockIdx.x * 256 + threadIdx.x) >> 5;
    int lane = threadIdx.x & 31;
    if (node >= N_NODES) return;
    int beg = rowptr[node], end = rowptr[node + 1];
    constexpr int E = F / 32;    // bf16 per lane: 8 (F=256) or 4 (F=128)
    float acc[E];
#pragma unroll
    for (int t = 0; t < E; t++) acc[t] = 0.f;

    auto addrow = [&](int s) {
        if (E == 8) {
            uint4 u = __ldg((const uint4*)(XH + (size_t)s * F) + lane);
            const uint32_t w[4] = { u.x, u.y, u.z, u.w };
#pragma unroll
            for (int t = 0; t < 4; t++) {
                float2 f = __bfloat1622float2(*(const __nv_bfloat162*)&w[t]);
                acc[2 * t] += f.x; acc[2 * t + 1] += f.y;
            }
        } else {
            uint2 u = __ldg((const uint2*)(XH + (size_t)s * F) + lane);
            const uint32_t w[2] = { u.x, u.y };
#pragma unroll
            for (int t = 0; t < 2; t++) {
                float2 f = __bfloat1622float2(*(const __nv_bfloat162*)&w[t]);
                acc[2 * t] += f.x; acc[2 * t + 1] += f.y;
            }
        }
    };
    int e = beg;
    for (; e + 7 < end; e += 8) {
        int s0 = csr[e],     s1 = csr[e + 1], s2 = csr[e + 2], s3 = csr[e + 3];
        int s4 = csr[e + 4], s5 = csr[e + 5], s6 = csr[e + 6], s7 = csr[e + 7];
        addrow(s0); addrow(s1); addrow(s2); addrow(s3);
        addrow(s4); addrow(s5); addrow(s6); addrow(s7);
    }
    for (; e + 1 < end; e += 2) {
        int s0 = csr[e], s1 = csr[e + 1];
        addrow(s0); addrow(s1);
    }
    for (; e < end; e++) addrow(csr[e]);

    float inv = deginv[node];
    uint32_t w[E / 2];
#pragma unroll
    for (int t = 0; t < E / 2; t++) {
        __nv_bfloat162 h2 = __floats2bfloat162_rn(acc[2 * t] * inv, acc[2 * t + 1] * inv);
        w[t] = *(uint32_t*)&h2;
    }
    if (E == 8)
        *((uint4*)(AH + (size_t)node * F) + lane) = make_uint4(w[0], w[1], w[2], w[3]);
    else
        *((uint2*)(AH + (size_t)node * F) + lane) = make_uint2(w[0], w[1]);
}

// =================== x -> bf16 conversion ====================================
__global__ void __launch_bounds__(256) k_split_x(const float4* __restrict__ X,
                                                 __nv_bfloat16* __restrict__ XH) {
    size_t i = (size_t)blockIdx.x * 256 + threadIdx.x;
    float4 v = X[i];
    __nv_bfloat162 a = __floats2bfloat162_rn(v.x, v.y);
    __nv_bfloat162 b = __floats2bfloat162_rn(v.z, v.w);
    ((uint2*)XH)[i] = make_uint2(*(uint32_t*)&a, *(uint32_t*)&b);
}

// ============ all weight transposes+splits in ONE launch =====================
struct PrepJobs {
    const float* W[9]; int K[9];
    __nv_bfloat16* OH[9]; __nv_bfloat16* OL[9];
};
__global__ void k_prep_w_all(PrepJobs jobs) {
    int j = blockIdx.y;
    int k = blockIdx.x;
    if (k >= jobs.K[j]) return;
    int n = threadIdx.x;
    float v = jobs.W[j][(size_t)k * HDIM + n];
    __nv_bfloat16 hi = __float2bfloat16(v);
    float lo = v - __bfloat162float(hi);
    jobs.OH[j][(size_t)n * jobs.K[j] + k] = hi;
    jobs.OL[j][(size_t)n * jobs.K[j] + k] = __float2bfloat16(lo);
}

// ====================== mma.sync bf16 pair-structured GEMM ===================
// C = sum_p A_p @ (B0_p [+ B1_p])^T + bias ; B1 only when useB1 (residual GEMM;
// main layer GEMMs drop the weight-lo term — BN absorbs its column bias).
// outmode 0: C bf16 (pre-norm raw) + fused BN column stats (stats in fp32)
// outmode 1: bf16 hi/lo split output (CH/CL)
struct Pair { const __nv_bfloat16* A; const __nv_bfloat16* B0; const __nv_bfloat16* B1; };
struct GArgs {
    Pair pr[2]; int npair; int K; const float* bias;
    __nv_bfloat16* C; __nv_bfloat16* CH; __nv_bfloat16* CL;
    float* cs; float* cs2; int outmode; int useB1;
};

#define LDS_STRIDE 72   // bf16 per smem row (64 data + 8 pad) = 144B
#define TBUF (128 * LDS_STRIDE)              // elems per tile buffer
#define SMEM_MMA (6 * TBUF * 2)              // bytes: 2-stage x (A + B0 + B1)

__global__ void __launch_bounds__(256) k_mma(GArgs ga) {
    extern __shared__ __align__(16) __nv_bfloat16 dynsmem[];
    __shared__ float s_sum[128], s_sq[128];

    const int tid = threadIdx.x;
    const int wid = tid >> 5, lane = tid & 31;
    const int wr = wid & 1, wc = wid >> 1;
    const int row0 = blockIdx.x * 128;
    const int col0 = blockIdx.y * 128;

    const uint32_t base = smem_to_u32(dynsmem);
    auto abase  = [&](int buf) { return base + (uint32_t)buf * (TBUF * 2); };
    auto b0base = [&](int buf) { return base + (uint32_t)(2 + buf) * (TBUF * 2); };
    auto b1base = [&](int buf) { return base + (uint32_t)(4 + buf) * (TBUF * 2); };

    const int K = ga.K;
    const int kpc = K >> 6;           // 64-wide chunks per pair
    const int nch = ga.npair * kpc;
    const int useB1 = ga.useB1;

    float acc[4][4][4];
#pragma unroll
    for (int mt = 0; mt < 4; mt++)
#pragma unroll
        for (int nt = 0; nt < 4; nt++)
#pragma unroll
            for (int q = 0; q < 4; q++) acc[mt][nt][q] = 0.f;

    const int a_r = lane & 15, a_c = lane >> 4;
    const int b_l = lane & 7, b_h = (lane >> 3) & 1;

    auto fill = [&](int buf, int ch) {
        int p = ch / kpc, kc = ch - p * kpc;
        const __nv_bfloat16* A  = ga.pr[p].A;
        const __nv_bfloat16* B0 = ga.pr[p].B0;
        const __nv_bfloat16* B1 = ga.pr[p].B1;
        uint32_t ab = abase(buf), b0b = b0base(buf), b1b = b1base(buf);
        int koff = kc * 64;
#pragma unroll
        for (int q = 0; q < 4; q++) {
            int i = tid + q * 256;            // 0..1023
            int r = i >> 3, pp = i & 7;
            int gr = row0 + r; if (gr > N_NODES - 1) gr = N_NODES - 1;
            uint32_t soff = r * (LDS_STRIDE * 2) + pp * 16;
            size_t goff = (size_t)(koff + pp * 8);
            cp16(ab  + soff, A  + ((size_t)gr * K + goff));
            cp16(b0b + soff, B0 + ((size_t)(col0 + r) * K + goff));
            if (useB1)
                cp16(b1b + soff, B1 + ((size_t)(col0 + r) * K + goff));
        }
        cp_commit();
    };

    fill(0, 0);
    for (int c = 0; c < nch; c++) {
        const int buf = c & 1;
        if (c + 1 < nch) {
            fill(buf ^ 1, c + 1);
            cp_wait<1>();
        } else {
            cp_wait<0>();
        }
        __syncthreads();

        const uint32_t ab = abase(buf);
        const uint32_t bb[2] = { b0base(buf), b1base(buf) };
#pragma unroll
        for (int ks = 0; ks < 4; ks++) {
            uint32_t a[4][4];
#pragma unroll
            for (int mt = 0; mt < 4; mt++)
                ldm_x4(a[mt], ab + ((wr * 64 + mt * 16 + a_r) * LDS_STRIDE
                                    + ks * 16 + a_c * 8) * 2);
            {
                uint32_t b[4][2];
#pragma unroll
                for (int nt = 0; nt < 4; nt++)
                    ldm_x2(b[nt], bb[0] + ((wc * 32 + nt * 8 + b_l) * LDS_STRIDE
                                           + ks * 16 + b_h * 8) * 2);
#pragma unroll
                for (int mt = 0; mt < 4; mt++)
#pragma unroll
                    for (int nt = 0; nt < 4; nt++)
                        mma_bf16(acc[mt][nt], a[mt], b[nt]);
            }
            if (useB1) {
                uint32_t b[4][2];
#pragma unroll
                for (int nt = 0; nt < 4; nt++)
                    ldm_x2(b[nt], bb[1] + ((wc * 32 + nt * 8 + b_l) * LDS_STRIDE
                                           + ks * 16 + b_h * 8) * 2);
#pragma unroll
                for (int mt = 0; mt < 4; mt++)
#pragma unroll
                    for (int nt = 0; nt < 4; nt++)
                        mma_bf16(acc[mt][nt], a[mt], b[nt]);
            }
        }
        __syncthreads();
    }

    // ---------------- epilogue ----------------
    if (ga.outmode == 0 && tid < 128) { s_sum[tid] = 0.f; s_sq[tid] = 0.f; }
    __syncthreads();

    const int er = lane >> 2;
    const int ec = (lane & 3) * 2;
#pragma unroll
    for (int nt = 0; nt < 4; nt++) {
        const int lcol = wc * 32 + nt * 8 + ec;
        const int col = col0 + lcol;
        const float b0 = ga.bias[col], b1 = ga.bias[col + 1];
        float ls0 = 0.f, ls1 = 0.f, lq0 = 0.f, lq1 = 0.f;
#pragma unroll
        for (int mt = 0; mt < 4; mt++) {
#pragma unroll
            for (int half = 0; half < 2; half++) {
                int row = row0 + wr * 64 + mt * 16 + er + half * 8;
                if (row >= N_NODES) continue;
                float v0 = acc[mt][nt][half * 2 + 0] + b0;
                float v1 = acc[mt][nt][half * 2 + 1] + b1;
                if (ga.outmode == 0) {
                    *(__nv_bfloat162*)(ga.C + (size_t)row * HDIM + col) =
                        __floats2bfloat162_rn(v0, v1);
                    ls0 += v0; ls1 += v1;
                    lq0 = fmaf(v0, v0, lq0); lq1 = fmaf(v1, v1, lq1);
                } else {
                    __nv_bfloat16 h0 = __float2bfloat16(v0), h1 = __float2bfloat16(v1);
                    *(__nv_bfloat162*)(ga.CH + (size_t)row * HDIM + col) =
                        __nv_bfloat162(h0, h1);
                    *(__nv_bfloat162*)(ga.CL + (size_t)row * HDIM + col) =
                        __nv_bfloat162(__float2bfloat16(v0 - __bfloat162float(h0)),
                                       __float2bfloat16(v1 - __bfloat162float(h1)));
                }
            }
        }
        if (ga.outmode == 0) {
            atomicAdd(&s_sum[lcol], ls0);     atomicAdd(&s_sum[lcol + 1], ls1);
            atomicAdd(&s_sq[lcol], lq0);      atomicAdd(&s_sq[lcol + 1], lq1);
        }
    }
    if (ga.outmode == 0) {
        __syncthreads();
        if (tid < 128) {
            atomicAdd(&ga.cs[col0 + tid], s_sum[tid]);
            atomicAdd(&ga.cs2[col0 + tid], s_sq[tid]);
        }
    }
}

// ============================ BN finalize / norm =============================
__global__ void k_bnfinal(const float* __restrict__ cs, const float* __restrict__ cs2,
                          const float* __restrict__ gamma, const float* __restrict__ beta,
                          float* __restrict__ scale, float* __restrict__ shift) {
    int j = threadIdx.x;
    const float invN = 1.0f / (float)N_NODES;
    float mu = cs[j] * invN;
    float var = cs2[j] * invN - mu * mu;
    float sc = gamma[j] * rsqrtf(var + EPS);
    scale[j] = sc;
    shift[j] = beta[j] - mu * sc;
}
// h_new = relu(raw*scale+shift) + (hh+hl); raw is bf16; store hi/lo split
__global__ void __launch_bounds__(256) k_norm(
    const __nv_bfloat16* __restrict__ RAW, const float* __restrict__ scale,
    const float* __restrict__ shift,
    __nv_bfloat16* __restrict__ HH, __nv_bfloat16* __restrict__ HL)
{
    size_t i = (size_t)blockIdx.x * 256 + threadIdx.x;
    int j = (int)((i & 63) << 2);
    uint2 rw = ((const uint2*)RAW)[i];
    uint2 hw = ((const uint2*)HH)[i];
    uint2 lw = ((const uint2*)HL)[i];
    float2 rv0 = __bfloat1622float2(*(const __nv_bfloat162*)&rw.x);
    float2 rv1 = __bfloat1622float2(*(const __nv_bfloat162*)&rw.y);
    float2 fh0 = __bfloat1622float2(*(const __nv_bfloat162*)&hw.x);
    float2 fh1 = __bfloat1622float2(*(const __nv_bfloat162*)&hw.y);
    float2 fl0 = __bfloat1622float2(*(const __nv_bfloat162*)&lw.x);
    float2 fl1 = __bfloat1622float2(*(const __nv_bfloat162*)&lw.y);
    float4 sc = *(const float4*)(scale + j);
    float4 sh = *(const float4*)(shift + j);
    float o0 = fmaxf(fmaf(rv0.x, sc.x, sh.x), 0.f) + fh0.x + fl0.x;
    float o1 = fmaxf(fmaf(rv0.y, sc.y, sh.y), 0.f) + fh0.y + fl0.y;
    float o2 = fmaxf(fmaf(rv1.x, sc.z, sh.z), 0.f) + fh1.x + fl1.x;
    float o3 = fmaxf(fmaf(rv1.y, sc.w, sh.w), 0.f) + fh1.y + fl1.y;
    __nv_bfloat16 h0 = __float2bfloat16(o0), h1 = __float2bfloat16(o1);
    __nv_bfloat16 h2b = __float2bfloat16(o2), h3 = __float2bfloat16(o3);
    __nv_bfloat162 oh0(h0, h1), oh1(h2b, h3);
    __nv_bfloat162 ol0(__float2bfloat16(o0 - __bfloat162float(h0)),
                       __float2bfloat16(o1 - __bfloat162float(h1)));
    __nv_bfloat162 ol1(__float2bfloat16(o2 - __bfloat162float(h2b)),
                       __float2bfloat16(o3 - __bfloat162float(h3)));
    ((uint2*)HH)[i] = make_uint2(*(uint32_t*)&oh0, *(uint32_t*)&oh1);
    ((uint2*)HL)[i] = make_uint2(*(uint32_t*)&ol0, *(uint32_t*)&ol1);
}

// ============================ pooling + head =================================
__device__ __forceinline__ int lower_bound_batch(const void* batch, long long val, int is64) {
    int lo = 0, hi = N_NODES;
    while (lo < hi) {
        int mid = (lo + hi) >> 1;
        long long b = is64 ? ((const long long*)batch)[mid]
                           : (long long)((const int*)batch)[mid];
        if (b < val) lo = mid + 1; else hi = mid;
    }
    return lo;
}
__global__ void k_pool(const __nv_bfloat16* __restrict__ HH,
                       const __nv_bfloat16* __restrict__ HL,
                       const void* __restrict__ batch, float* __restrict__ pool) {
    int g = blockIdx.x;
    __shared__ int slo, shi;
    if (threadIdx.x == 0) {
        int is64 = g_is64;
        slo = lower_bound_batch(batch, g, is64);
        shi = lower_bound_batch(batch, g + 1, is64);
    }
    __syncthreads();
    int j = threadIdx.x;           // 0..127 -> columns 2j, 2j+1
    float s0 = 0.f, s1 = 0.f;
    for (int n = slo; n < shi; n++) {
        size_t o = (size_t)n * (HDIM / 2) + j;
        float2 fh = __bfloat1622float2(((const __nv_bfloat162*)HH)[o]);
        float2 fl = __bfloat1622float2(((const __nv_bfloat162*)HL)[o]);
        s0 += fh.x + fl.x; s1 += fh.y + fl.y;
    }
    float inv = 1.0f / (float)max(shi - slo, 1);
    pool[g * HDIM + 2 * j]     = s0 * inv;
    pool[g * HDIM + 2 * j + 1] = s1 * inv;
}
__global__ void k_final(const float* __restrict__ pool, const float* __restrict__ linW,
                        const float* __restrict__ linb, float* __restrict__ out) {
    int g = blockIdx.x * 8 + (threadIdx.x >> 5);
    int lane = threadIdx.x & 31;
    if (g >= N_GRAPHS) return;
    float s = 0.f;
#pragma unroll
    for (int q = 0; q < 8; q++) {
        int k = lane + q * 32;
        s = fmaf(pool[g * HDIM + k], linW[k], s);
    }
#pragma unroll
    for (int o = 16; o > 0; o >>= 1) s += __shfl_xor_sync(0xFFFFFFFFu, s, o);
    if (lane == 0) out[g] = s + linb[0];
}

// ============================ host orchestration ============================
extern "C" void kernel_launch(void* const* d_in, const int* in_sizes, int n_in,
                              void* d_out, int out_size) {
    const float* x   = (const float*)d_in[0];
    const void*  ei  = d_in[1];
    const void*  bat = d_in[2];
    const float* W[4][5];
    for (int b = 0; b < 4; b++)
        for (int k = 0; k < 5; k++)
            W[b][k] = (const float*)d_in[3 + b * 5 + k];
    const float* resW = (const float*)d_in[23];
    const float* resb = (const float*)d_in[24];
    const float* linW = (const float*)d_in[25];
    const float* linb = (const float*)d_in[26];
    float* out = (float*)d_out;

    void* p;
    cudaGetSymbolAddress(&p, g_h2);     __nv_bfloat16* h2b = (__nv_bfloat16*)p;
    cudaGetSymbolAddress(&p, g_hh);     __nv_bfloat16* hh = (__nv_bfloat16*)p;
    cudaGetSymbolAddress(&p, g_hl);     __nv_bfloat16* hl = (__nv_bfloat16*)p;
    cudaGetSymbolAddress(&p, g_aggh);   __nv_bfloat16* aggh = (__nv_bfloat16*)p;
    cudaGetSymbolAddress(&p, g_xh);     __nv_bfloat16* xh = (__nv_bfloat16*)p;
    cudaGetSymbolAddress(&p, g_bth);    __nv_bfloat16* bth = (__nv_bfloat16*)p;
    cudaGetSymbolAddress(&p, g_btl);    __nv_bfloat16* btl = (__nv_bfloat16*)p;
    cudaGetSymbolAddress(&p, g_deg);    int* deg = (int*)p;
    cudaGetSymbolAddress(&p, g_deginv); float* deginv = (float*)p;
    cudaGetSymbolAddress(&p, g_rowptr); int* rowptr = (int*)p;
    cudaGetSymbolAddress(&p, g_cursor); int* cursor = (int*)p;
    cudaGetSymbolAddress(&p, g_csr);    int* csr = (int*)p;
    cudaGetSymbolAddress(&p, g_blksum); int* blksum = (int*)p;
    cudaGetSymbolAddress(&p, g_blkoff); int* blkoff = (int*)p;
    cudaGetSymbolAddress(&p, g_colsum);   float* colsum = (float*)p;
    cudaGetSymbolAddress(&p, g_colsumsq); float* colsumsq = (float*)p;
    cudaGetSymbolAddress(&p, g_scale);  float* scale = (float*)p;
    cudaGetSymbolAddress(&p, g_shift);  float* shift = (float*)p;
    cudaGetSymbolAddress(&p, g_pool);   float* pool = (float*)p;

    static cudaStream_t s1 = nullptr;
    static cudaEvent_t evFork = nullptr, evXh = nullptr, evSide = nullptr;
    if (!s1) {
        cudaStreamCreateWithFlags(&s1, cudaStreamNonBlocking);
        cudaEventCreateWithFlags(&evFork, cudaEventDisableTiming);
        cudaEventCreateWithFlags(&evXh, cudaEventDisableTiming);
        cudaEventCreateWithFlags(&evSide, cudaEventDisableTiming);
        cudaFuncSetAttribute(k_mma, cudaFuncAttributeMaxDynamicSharedMemorySize, SMEM_MMA);
    }

    auto bt_h = [&](int slot) { return bth + (size_t)slot * HDIM * HDIM; };
    auto bt_l = [&](int slot) { return btl + (size_t)slot * HDIM * HDIM; };

    const int agg_blocks = (N_NODES * 32 + 255) / 256;
    const dim3 gemm_grid((N_NODES + 127) / 128, HDIM / 128);
    const int norm_grid = (N_NODES * HDIM / 4 + 255) / 256;

    // ---- fork: CSR chain on stream 0, prep chain + res-GEMM on s1 ----
    cudaEventRecord(evFork, 0);
    cudaStreamWaitEvent(s1, evFork, 0);

    // stream 0: CSR build
    k_prep0<<<(N_NODES + 255) / 256, 256>>>((const int*)ei);
    k_degree<<<(N_EDGES + 255) / 256, 256>>>(ei, deg);
    k_scan_partial<<<NB, SB>>>(deg, blksum);
    k_scan_blk<<<1, 32>>>(blksum, blkoff, rowptr);
    k_scan_final<<<NB, SB>>>(deg, blkoff, rowptr, deginv);
    k_fillcsr<<<(N_EDGES + 255) / 256, 256>>>(ei, rowptr, cursor, csr);

    // stream s1: operand prep + residual GEMM
    k_split_x<<<(N_NODES * F_IN / 4 + 255) / 256, 256, 0, s1>>>((const float4*)x, xh);
    cudaEventRecord(evXh, s1);
    {
        PrepJobs j;
        j.W[0] = W[0][0]; j.K[0] = F_IN; j.OH[0] = bt_h(0); j.OL[0] = bt_l(0);
        j.W[1] = W[0][2]; j.K[1] = F_IN; j.OH[1] = bt_h(1); j.OL[1] = bt_l(1);
        j.W[2] = resW;    j.K[2] = F_IN; j.OH[2] = bt_h(2); j.OL[2] = bt_l(2);
        for (int b = 1; b < 4; b++) {
            int s0 = 3 + (b - 1) * 2;
            j.W[s0] = W[b][0]; j.K[s0] = HDIM; j.OH[s0] = bt_h(s0); j.OL[s0] = bt_l(s0);
            j.W[s0 + 1] = W[b][2]; j.K[s0 + 1] = HDIM; j.OH[s0 + 1] = bt_h(s0 + 1); j.OL[s0 + 1] = bt_l(s0 + 1);
        }
        k_prep_w_all<<<dim3(HDIM, 9), 256, 0, s1>>>(j);
    }
    {   // residual GEMM: (x @ resW + resb) -> hh/hl split (keeps weight-lo: no BN after)
        GArgs a = {};
        a.pr[0] = { xh, bt_h(2), bt_l(2) };
        a.npair = 1; a.K = F_IN; a.bias = resb;
        a.CH = hh; a.CL = hl; a.outmode = 1; a.useB1 = 1;
        k_mma<<<gemm_grid, 256, SMEM_MMA, s1>>>(a);
    }
    cudaEventRecord(evSide, s1);

    // stream 0: layer-1 aggregation (needs only xh + csr) — overlaps res-GEMM
    cudaStreamWaitEvent(0, evXh, 0);
    k_agg<F_IN><<<agg_blocks, 256>>>(xh, rowptr, csr, deginv, aggh);
    cudaStreamWaitEvent(0, evSide, 0);   // join: need hh/hl before layer-1 norm path

    // ---- block 1 ----
    {
        GArgs a = {};
        a.pr[0] = { aggh, bt_h(0), nullptr };
        a.pr[1] = { xh,   bt_h(1), nullptr };
        a.npair = 2; a.K = F_IN; a.bias = W[0][1];
        a.C = h2b; a.cs = colsum; a.cs2 = colsumsq; a.outmode = 0; a.useB1 = 0;
        k_mma<<<gemm_grid, 256, SMEM_MMA>>>(a);
    }
    k_bnfinal<<<1, 256>>>(colsum, colsumsq, W[0][3], W[0][4], scale, shift);
    k_norm<<<norm_grid, 256>>>(h2b, scale, shift, hh, hl);

    // ---- blocks 2..4 ----
    for (int b = 1; b < 4; b++) {
        int sl = 3 + (b - 1) * 2, sr = sl + 1;
        k_agg<HDIM><<<agg_blocks, 256>>>(hh, rowptr, csr, deginv, aggh);
        GArgs a = {};
        a.pr[0] = { aggh, bt_h(sl), nullptr };
        a.pr[1] = { hh,   bt_h(sr), nullptr };
        a.npair = 2; a.K = HDIM; a.bias = W[b][1];
        a.C = h2b; a.cs = colsum; a.cs2 = colsumsq; a.outmode = 0; a.useB1 = 0;
        k_mma<<<gemm_grid, 256, SMEM_MMA>>>(a);
        k_bnfinal<<<1, 256>>>(colsum, colsumsq, W[b][3], W[b][4], scale, shift);
        k_norm<<<norm_grid, 256>>>(h2b, scale, shift, hh, hl);
    }

    // ---- pooling + head ----
    k_pool<<<N_GRAPHS, 128>>>(hh, hl, bat, pool);
    k_final<<<N_GRAPHS / 8, 256>>>(pool, linW, linb, out);
}

// round 15
// speedup vs baseline: 1.2308x; 1.2308x over previous
#include <cuda_runtime.h>
#include <cuda_bf16.h>
#include <cstdint>

#define N_NODES 100000
#define N_EDGES 1600000
#define N_GRAPHS 256
#define F_IN 128
#define HDIM 256
#define EPS 1e-5f

#define SB 512
#define NB ((N_NODES + SB - 1) / SB)   // 196

// ========================== PTX helpers (sm_80-class only) ===================
__device__ __forceinline__ uint32_t smem_to_u32(const void* p) {
    uint32_t a;
    asm("{ .reg .u64 t; cvta.to.shared.u64 t, %1; cvt.u32.u64 %0, t; }" : "=r"(a) : "l"(p));
    return a;
}
__device__ __forceinline__ void cp16(uint32_t d, const void* s) {
    asm volatile("cp.async.cg.shared.global [%0], [%1], 16;" :: "r"(d), "l"(s));
}
__device__ __forceinline__ void cp_commit() { asm volatile("cp.async.commit_group;" ::: "memory"); }
template <int N> __device__ __forceinline__ void cp_wait() {
    asm volatile("cp.async.wait_group %0;" :: "n"(N) : "memory");
}
__device__ __forceinline__ void ldm_x4(uint32_t* d, uint32_t addr) {
    asm volatile("ldmatrix.sync.aligned.m8n8.x4.shared.b16 {%0,%1,%2,%3}, [%4];"
                 : "=r"(d[0]), "=r"(d[1]), "=r"(d[2]), "=r"(d[3]) : "r"(addr));
}
__device__ __forceinline__ void ldm_x2(uint32_t* d, uint32_t addr) {
    asm volatile("ldmatrix.sync.aligned.m8n8.x2.shared.b16 {%0,%1}, [%2];"
                 : "=r"(d[0]), "=r"(d[1]) : "r"(addr));
}
__device__ __forceinline__ void mma_bf16(float* c, const uint32_t* a, const uint32_t* b) {
    asm volatile("mma.sync.aligned.m16n8k16.row.col.f32.bf16.bf16.f32 "
                 "{%0,%1,%2,%3}, {%4,%5,%6,%7}, {%8,%9}, {%0,%1,%2,%3};"
                 : "+f"(c[0]), "+f"(c[1]), "+f"(c[2]), "+f"(c[3])
                 : "r"(a[0]), "r"(a[1]), "r"(a[2]), "r"(a[3]), "r"(b[0]), "r"(b[1]));
}

// ============================ scratch (static) ================================
// NOTE: buffer set/sizes/order preserved from the champion build — layout matters
// (R8/R9 showed deleting g_hl cost ~240us). g_h2 stays declared fp32-sized; we
// store bf16 into its first half. g_btl stays allocated+written even though the
// main GEMMs no longer read it (residual GEMM still does).
__device__ __align__(256) float g_h2[(size_t)N_NODES * HDIM];
__device__ __align__(256) __nv_bfloat16 g_hh [(size_t)N_NODES * HDIM];
__device__ __align__(256) __nv_bfloat16 g_hl [(size_t)N_NODES * HDIM];
__device__ __align__(256) __nv_bfloat16 g_aggh[(size_t)N_NODES * HDIM];
__device__ __align__(256) __nv_bfloat16 g_xh[(size_t)N_NODES * F_IN];
__device__ __align__(256) __nv_bfloat16 g_bth[9][HDIM * HDIM];
__device__ __align__(256) __nv_bfloat16 g_btl[9][HDIM * HDIM];
__device__ int   g_deg[N_NODES];
__device__ float g_deginv[N_NODES];
__device__ int   g_rowptr[N_NODES + 1];
__device__ int   g_cursor[N_NODES];
__device__ int   g_csr[N_EDGES];
__device__ int   g_blksum[NB];
__device__ int   g_blkoff[NB];
__device__ float g_colsum[HDIM];
__device__ float g_colsumsq[HDIM];
__device__ float g_scale[HDIM];
__device__ float g_shift[HDIM];
__device__ float g_pool[N_GRAPHS * HDIM];
__device__ int   g_is64;

// =================== prologue: dtype detect + zero deg/cursor ================
__global__ void k_prep0(const int* __restrict__ ei32) {
    int i = blockIdx.x * 256 + threadIdx.x;
    if (i < N_NODES) { g_deg[i] = 0; g_cursor[i] = 0; }
    if (blockIdx.x == 0) {
        __shared__ int nz;
        if (threadIdx.x == 0) nz = 0;
        __syncthreads();
        int acc = 0;
#pragma unroll
        for (int q = 0; q < 4; q++) acc |= ei32[2 * (threadIdx.x * 4 + q) + 1];
        if (acc) atomicOr(&nz, 1);
        __syncthreads();
        if (threadIdx.x == 0) g_is64 = (nz == 0) ? 1 : 0;
    }
}
__device__ __forceinline__ long long load_idx(const void* p, long long i, int is64) {
    return is64 ? ((const long long*)p)[i] : (long long)((const int*)p)[i];
}
__global__ void k_degree(const void* __restrict__ ei, int* __restrict__ deg) {
    int e = blockIdx.x * blockDim.x + threadIdx.x;
    if (e >= N_EDGES) return;
    int dst = (int)load_idx(ei, (long long)N_EDGES + e, g_is64);
    atomicAdd(&deg[dst], 1);
}
__global__ void k_scan_partial(const int* __restrict__ deg, int* __restrict__ blksum) {
    __shared__ int sh[SB];
    int i = blockIdx.x * SB + threadIdx.x;
    sh[threadIdx.x] = (i < N_NODES) ? deg[i] : 0;
    __syncthreads();
    for (int o = SB / 2; o > 0; o >>= 1) {
        if (threadIdx.x < o) sh[threadIdx.x] += sh[threadIdx.x + o];
        __syncthreads();
    }
    if (threadIdx.x == 0) blksum[blockIdx.x] = sh[0];
}
__global__ void k_scan_blk(const int* __restrict__ blksum, int* __restrict__ blkoff,
                           int* __restrict__ rowptr) {
    if (threadIdx.x == 0) {
        int a = 0;
        for (int b = 0; b < NB; b++) { blkoff[b] = a; a += blksum[b]; }
        rowptr[N_NODES] = a;
    }
}
__global__ void k_scan_final(const int* __restrict__ deg, const int* __restrict__ blkoff,
                             int* __restrict__ rowptr, float* __restrict__ deginv) {
    __shared__ int sh[SB];
    int i = blockIdx.x * SB + threadIdx.x;
    int v = (i < N_NODES) ? deg[i] : 0;
    sh[threadIdx.x] = v;
    __syncthreads();
    for (int o = 1; o < SB; o <<= 1) {
        int t = (threadIdx.x >= o) ? sh[threadIdx.x - o] : 0;
        __syncthreads();
        sh[threadIdx.x] += t;
        __syncthreads();
    }
    if (i < N_NODES) {
        rowptr[i] = blkoff[blockIdx.x] + sh[threadIdx.x] - v;
        deginv[i] = 1.0f / (float)max(v, 1);
    }
}
__global__ void k_fillcsr(const void* __restrict__ ei, const int* __restrict__ rowptr,
                          int* __restrict__ cursor, int* __restrict__ csr) {
    int e = blockIdx.x * blockDim.x + threadIdx.x;
    if (e >= N_EDGES) return;
    int is64 = g_is64;
    int src = (int)load_idx(ei, e, is64);
    int dst = (int)load_idx(ei, (long long)N_EDGES + e, is64);
    int p = atomicAdd(&cursor[dst], 1);
    csr[rowptr[dst] + p] = src;
}

// ========== aggregation: CSR gather (16B vector loads) -> bf16 mean ==========
template <int F>
__global__ void __launch_bounds__(256) k_agg(
    const __nv_bfloat16* __restrict__ XH, const int* __restrict__ rowptr,
    const int* __restrict__ csr, const float* __restrict__ deginv,
    __nv_bfloat16* __restrict__ AH)
{
    if (blockIdx.x == 0) { g_colsum[threadIdx.x] = 0.f; g_colsumsq[threadIdx.x] = 0.f; }
    int node = (blockIdx.x * 256 + threadIdx.x) >> 5;
    int lane = threadIdx.x & 31;
    if (node >= N_NODES) return;
    int beg = rowptr[node], end = rowptr[node + 1];
    constexpr int E = F / 32;
    float acc[E];
#pragma unroll
    for (int t = 0; t < E; t++) acc[t] = 0.f;

    auto addrow = [&](int s) {
        if (E == 8) {
            uint4 u = __ldg((const uint4*)(XH + (size_t)s * F) + lane);
            const uint32_t w[4] = { u.x, u.y, u.z, u.w };
#pragma unroll
            for (int t = 0; t < 4; t++) {
                float2 f = __bfloat1622float2(*(const __nv_bfloat162*)&w[t]);
                acc[2 * t] += f.x; acc[2 * t + 1] += f.y;
            }
        } else {
            uint2 u = __ldg((const uint2*)(XH + (size_t)s * F) + lane);
            const uint32_t w[2] = { u.x, u.y };
#pragma unroll
            for (int t = 0; t < 2; t++) {
                float2 f = __bfloat1622float2(*(const __nv_bfloat162*)&w[t]);
                acc[2 * t] += f.x; acc[2 * t + 1] += f.y;
            }
        }
    };
    int e = beg;
    for (; e + 7 < end; e += 8) {
        int s0 = csr[e],     s1 = csr[e + 1], s2 = csr[e + 2], s3 = csr[e + 3];
        int s4 = csr[e + 4], s5 = csr[e + 5], s6 = csr[e + 6], s7 = csr[e + 7];
        addrow(s0); addrow(s1); addrow(s2); addrow(s3);
        addrow(s4); addrow(s5); addrow(s6); addrow(s7);
    }
    for (; e + 1 < end; e += 2) {
        int s0 = csr[e], s1 = csr[e + 1];
        addrow(s0); addrow(s1);
    }
    for (; e < end; e++) addrow(csr[e]);

    float inv = deginv[node];
    uint32_t w[E / 2];
#pragma unroll
    for (int t = 0; t < E / 2; t++) {
        __nv_bfloat162 h2 = __floats2bfloat162_rn(acc[2 * t] * inv, acc[2 * t + 1] * inv);
        w[t] = *(uint32_t*)&h2;
    }
    if (E == 8)
        *((uint4*)(AH + (size_t)node * F) + lane) = make_uint4(w[0], w[1], w[2], w[3]);
    else
        *((uint2*)(AH + (size_t)node * F) + lane) = make_uint2(w[0], w[1]);
}

// =================== x -> bf16 conversion ====================================
__global__ void __launch_bounds__(256) k_split_x(const float4* __restrict__ X,
                                                 __nv_bfloat16* __restrict__ XH) {
    size_t i = (size_t)blockIdx.x * 256 + threadIdx.x;
    float4 v = X[i];
    __nv_bfloat162 a = __floats2bfloat162_rn(v.x, v.y);
    __nv_bfloat162 b = __floats2bfloat162_rn(v.z, v.w);
    ((uint2*)XH)[i] = make_uint2(*(uint32_t*)&a, *(uint32_t*)&b);
}

// ============ all weight transposes+splits in ONE launch =====================
struct PrepJobs {
    const float* W[9]; int K[9];
    __nv_bfloat16* OH[9]; __nv_bfloat16* OL[9];
};
__global__ void k_prep_w_all(PrepJobs jobs) {
    int j = blockIdx.y;
    int k = blockIdx.x;
    if (k >= jobs.K[j]) return;
    int n = threadIdx.x;
    float v = jobs.W[j][(size_t)k * HDIM + n];
    __nv_bfloat16 hi = __float2bfloat16(v);
    float lo = v - __bfloat162float(hi);
    jobs.OH[j][(size_t)n * jobs.K[j] + k] = hi;
    jobs.OL[j][(size_t)n * jobs.K[j] + k] = __float2bfloat16(lo);
}

// ====================== mma.sync bf16 pair-structured GEMM ===================
// C = sum_p A_p @ (B0_p [+ B1_p])^T + bias ; USEB1 compile-time (residual keeps
// weight-lo; main layer GEMMs drop it — BN absorbs the column bias).
// outmode 0: C bf16 (pre-norm raw) + fused BN column stats (stats in fp32)
// outmode 1: bf16 hi/lo split output (CH/CL)
struct Pair { const __nv_bfloat16* A; const __nv_bfloat16* B0; const __nv_bfloat16* B1; };
struct GArgs {
    Pair pr[2]; int npair; int K; const float* bias;
    __nv_bfloat16* C; __nv_bfloat16* CH; __nv_bfloat16* CL;
    float* cs; float* cs2; int outmode;
};

#define LDS_STRIDE 72   // bf16 per smem row (64 data + 8 pad) = 144B
#define TBUF (128 * LDS_STRIDE)              // elems per tile buffer
#define SMEM_MMA (6 * TBUF * 2)              // bytes: 2-stage x (A + B0 + B1)

template <bool USEB1>
__global__ void __launch_bounds__(256) k_mma(GArgs ga) {
    extern __shared__ __align__(16) __nv_bfloat16 dynsmem[];
    __shared__ float s_sum[128], s_sq[128];

    const int tid = threadIdx.x;
    const int wid = tid >> 5, lane = tid & 31;
    const int wr = wid & 1, wc = wid >> 1;
    const int row0 = blockIdx.x * 128;
    const int col0 = blockIdx.y * 128;

    const uint32_t base = smem_to_u32(dynsmem);
    auto abase  = [&](int buf) { return base + (uint32_t)buf * (TBUF * 2); };
    auto b0base = [&](int buf) { return base + (uint32_t)(2 + buf) * (TBUF * 2); };
    auto b1base = [&](int buf) { return base + (uint32_t)(4 + buf) * (TBUF * 2); };

    const int K = ga.K;
    const int kpc = K >> 6;           // 64-wide chunks per pair
    const int nch = ga.npair * kpc;

    float acc[4][4][4];
#pragma unroll
    for (int mt = 0; mt < 4; mt++)
#pragma unroll
        for (int nt = 0; nt < 4; nt++)
#pragma unroll
            for (int q = 0; q < 4; q++) acc[mt][nt][q] = 0.f;

    const int a_r = lane & 15, a_c = lane >> 4;
    const int b_l = lane & 7, b_h = (lane >> 3) & 1;

    auto fill = [&](int buf, int ch) {
        int p = ch / kpc, kc = ch - p * kpc;
        const __nv_bfloat16* A  = ga.pr[p].A;
        const __nv_bfloat16* B0 = ga.pr[p].B0;
        const __nv_bfloat16* B1 = ga.pr[p].B1;
        uint32_t ab = abase(buf), b0b = b0base(buf), b1b = b1base(buf);
        int koff = kc * 64;
#pragma unroll
        for (int q = 0; q < 4; q++) {
            int i = tid + q * 256;            // 0..1023
            int r = i >> 3, pp = i & 7;
            int gr = row0 + r; if (gr > N_NODES - 1) gr = N_NODES - 1;
            uint32_t soff = r * (LDS_STRIDE * 2) + pp * 16;
            size_t goff = (size_t)(koff + pp * 8);
            cp16(ab  + soff, A  + ((size_t)gr * K + goff));
            cp16(b0b + soff, B0 + ((size_t)(col0 + r) * K + goff));
            if (USEB1)
                cp16(b1b + soff, B1 + ((size_t)(col0 + r) * K + goff));
        }
        cp_commit();
    };

    fill(0, 0);
    for (int c = 0; c < nch; c++) {
        const int buf = c & 1;
        if (c + 1 < nch) {
            fill(buf ^ 1, c + 1);
            cp_wait<1>();
        } else {
            cp_wait<0>();
        }
        __syncthreads();

        const uint32_t ab = abase(buf);
        const uint32_t bb[2] = { b0base(buf), b1base(buf) };
#pragma unroll
        for (int ks = 0; ks < 4; ks++) {
            uint32_t a[4][4];
#pragma unroll
            for (int mt = 0; mt < 4; mt++)
                ldm_x4(a[mt], ab + ((wr * 64 + mt * 16 + a_r) * LDS_STRIDE
                                    + ks * 16 + a_c * 8) * 2);
#pragma unroll
            for (int g = 0; g < (USEB1 ? 2 : 1); g++) {
                uint32_t b[4][2];
#pragma unroll
                for (int nt = 0; nt < 4; nt++)
                    ldm_x2(b[nt], bb[g] + ((wc * 32 + nt * 8 + b_l) * LDS_STRIDE
                                           + ks * 16 + b_h * 8) * 2);
#pragma unroll
                for (int mt = 0; mt < 4; mt++)
#pragma unroll
                    for (int nt = 0; nt < 4; nt++)
                        mma_bf16(acc[mt][nt], a[mt], b[nt]);
            }
        }
        __syncthreads();
    }

    // ---------------- epilogue ----------------
    if (ga.outmode == 0 && tid < 128) { s_sum[tid] = 0.f; s_sq[tid] = 0.f; }
    __syncthreads();

    const int er = lane >> 2;
    const int ec = (lane & 3) * 2;
#pragma unroll
    for (int nt = 0; nt < 4; nt++) {
        const int lcol = wc * 32 + nt * 8 + ec;
        const int col = col0 + lcol;
        const float b0 = ga.bias[col], b1 = ga.bias[col + 1];
        float ls0 = 0.f, ls1 = 0.f, lq0 = 0.f, lq1 = 0.f;
#pragma unroll
        for (int mt = 0; mt < 4; mt++) {
#pragma unroll
            for (int half = 0; half < 2; half++) {
                int row = row0 + wr * 64 + mt * 16 + er + half * 8;
                if (row >= N_NODES) continue;
                float v0 = acc[mt][nt][half * 2 + 0] + b0;
                float v1 = acc[mt][nt][half * 2 + 1] + b1;
                if (ga.outmode == 0) {
                    *(__nv_bfloat162*)(ga.C + (size_t)row * HDIM + col) =
                        __floats2bfloat162_rn(v0, v1);
                    ls0 += v0; ls1 += v1;
                    lq0 = fmaf(v0, v0, lq0); lq1 = fmaf(v1, v1, lq1);
                } else {
                    __nv_bfloat16 h0 = __float2bfloat16(v0), h1 = __float2bfloat16(v1);
                    *(__nv_bfloat162*)(ga.CH + (size_t)row * HDIM + col) =
                        __nv_bfloat162(h0, h1);
                    *(__nv_bfloat162*)(ga.CL + (size_t)row * HDIM + col) =
                        __nv_bfloat162(__float2bfloat16(v0 - __bfloat162float(h0)),
                                       __float2bfloat16(v1 - __bfloat162float(h1)));
                }
            }
        }
        if (ga.outmode == 0) {
            atomicAdd(&s_sum[lcol], ls0);     atomicAdd(&s_sum[lcol + 1], ls1);
            atomicAdd(&s_sq[lcol], lq0);      atomicAdd(&s_sq[lcol + 1], lq1);
        }
    }
    if (ga.outmode == 0) {
        __syncthreads();
        if (tid < 128) {
            atomicAdd(&ga.cs[col0 + tid], s_sum[tid]);
            atomicAdd(&ga.cs2[col0 + tid], s_sq[tid]);
        }
    }
}

// ============================ BN finalize / norm =============================
__global__ void k_bnfinal(const float* __restrict__ cs, const float* __restrict__ cs2,
                          const float* __restrict__ gamma, const float* __restrict__ beta,
                          float* __restrict__ scale, float* __restrict__ shift) {
    int j = threadIdx.x;
    const float invN = 1.0f / (float)N_NODES;
    float mu = cs[j] * invN;
    float var = cs2[j] * invN - mu * mu;
    float sc = gamma[j] * rsqrtf(var + EPS);
    scale[j] = sc;
    shift[j] = beta[j] - mu * sc;
}
// h_new = relu(raw*scale+shift) + (hh+hl); raw is bf16; store hi/lo split
__global__ void __launch_bounds__(256) k_norm(
    const __nv_bfloat16* __restrict__ RAW, const float* __restrict__ scale,
    const float* __restrict__ shift,
    __nv_bfloat16* __restrict__ HH, __nv_bfloat16* __restrict__ HL)
{
    size_t i = (size_t)blockIdx.x * 256 + threadIdx.x;
    int j = (int)((i & 63) << 2);
    uint2 rw = ((const uint2*)RAW)[i];
    uint2 hw = ((const uint2*)HH)[i];
    uint2 lw = ((const uint2*)HL)[i];
    float2 rv0 = __bfloat1622float2(*(const __nv_bfloat162*)&rw.x);
    float2 rv1 = __bfloat1622float2(*(const __nv_bfloat162*)&rw.y);
    float2 fh0 = __bfloat1622float2(*(const __nv_bfloat162*)&hw.x);
    float2 fh1 = __bfloat1622float2(*(const __nv_bfloat162*)&hw.y);
    float2 fl0 = __bfloat1622float2(*(const __nv_bfloat162*)&lw.x);
    float2 fl1 = __bfloat1622float2(*(const __nv_bfloat162*)&lw.y);
    float4 sc = *(const float4*)(scale + j);
    float4 sh = *(const float4*)(shift + j);
    float o0 = fmaxf(fmaf(rv0.x, sc.x, sh.x), 0.f) + fh0.x + fl0.x;
    float o1 = fmaxf(fmaf(rv0.y, sc.y, sh.y), 0.f) + fh0.y + fl0.y;
    float o2 = fmaxf(fmaf(rv1.x, sc.z, sh.z), 0.f) + fh1.x + fl1.x;
    float o3 = fmaxf(fmaf(rv1.y, sc.w, sh.w), 0.f) + fh1.y + fl1.y;
    __nv_bfloat16 h0 = __float2bfloat16(o0), h1 = __float2bfloat16(o1);
    __nv_bfloat16 h2b = __float2bfloat16(o2), h3 = __float2bfloat16(o3);
    __nv_bfloat162 oh0(h0, h1), oh1(h2b, h3);
    __nv_bfloat162 ol0(__float2bfloat16(o0 - __bfloat162float(h0)),
                       __float2bfloat16(o1 - __bfloat162float(h1)));
    __nv_bfloat162 ol1(__float2bfloat16(o2 - __bfloat162float(h2b)),
                       __float2bfloat16(o3 - __bfloat162float(h3)));
    ((uint2*)HH)[i] = make_uint2(*(uint32_t*)&oh0, *(uint32_t*)&oh1);
    ((uint2*)HL)[i] = make_uint2(*(uint32_t*)&ol0, *(uint32_t*)&ol1);
}

// ============================ pooling + head =================================
__device__ __forceinline__ int lower_bound_batch(const void* batch, long long val, int is64) {
    int lo = 0, hi = N_NODES;
    while (lo < hi) {
        int mid = (lo + hi) >> 1;
        long long b = is64 ? ((const long long*)batch)[mid]
                           : (long long)((const int*)batch)[mid];
        if (b < val) lo = mid + 1; else hi = mid;
    }
    return lo;
}
__global__ void k_pool(const __nv_bfloat16* __restrict__ HH,
                       const __nv_bfloat16* __restrict__ HL,
                       const void* __restrict__ batch, float* __restrict__ pool) {
    int g = blockIdx.x;
    __shared__ int slo, shi;
    if (threadIdx.x == 0) {
        int is64 = g_is64;
        slo = lower_bound_batch(batch, g, is64);
        shi = lower_bound_batch(batch, g + 1, is64);
    }
    __syncthreads();
    int j = threadIdx.x;
    float s0 = 0.f, s1 = 0.f;
    for (int n = slo; n < shi; n++) {
        size_t o = (size_t)n * (HDIM / 2) + j;
        float2 fh = __bfloat1622float2(((const __nv_bfloat162*)HH)[o]);
        float2 fl = __bfloat1622float2(((const __nv_bfloat162*)HL)[o]);
        s0 += fh.x + fl.x; s1 += fh.y + fl.y;
    }
    float inv = 1.0f / (float)max(shi - slo, 1);
    pool[g * HDIM + 2 * j]     = s0 * inv;
    pool[g * HDIM + 2 * j + 1] = s1 * inv;
}
__global__ void k_final(const float* __restrict__ pool, const float* __restrict__ linW,
                        const float* __restrict__ linb, float* __restrict__ out) {
    int g = blockIdx.x * 8 + (threadIdx.x >> 5);
    int lane = threadIdx.x & 31;
    if (g >= N_GRAPHS) return;
    float s = 0.f;
#pragma unroll
    for (int q = 0; q < 8; q++) {
        int k = lane + q * 32;
        s = fmaf(pool[g * HDIM + k], linW[k], s);
    }
#pragma unroll
    for (int o = 16; o > 0; o >>= 1) s += __shfl_xor_sync(0xFFFFFFFFu, s, o);
    if (lane == 0) out[g] = s + linb[0];
}

// ============================ host orchestration ============================
extern "C" void kernel_launch(void* const* d_in, const int* in_sizes, int n_in,
                              void* d_out, int out_size) {
    const float* x   = (const float*)d_in[0];
    const void*  ei  = d_in[1];
    const void*  bat = d_in[2];
    const float* W[4][5];
    for (int b = 0; b < 4; b++)
        for (int k = 0; k < 5; k++)
            W[b][k] = (const float*)d_in[3 + b * 5 + k];
    const float* resW = (const float*)d_in[23];
    const float* resb = (const float*)d_in[24];
    const float* linW = (const float*)d_in[25];
    const float* linb = (const float*)d_in[26];
    float* out = (float*)d_out;

    void* p;
    cudaGetSymbolAddress(&p, g_h2);     __nv_bfloat16* h2b = (__nv_bfloat16*)p;
    cudaGetSymbolAddress(&p, g_hh);     __nv_bfloat16* hh = (__nv_bfloat16*)p;
    cudaGetSymbolAddress(&p, g_hl);     __nv_bfloat16* hl = (__nv_bfloat16*)p;
    cudaGetSymbolAddress(&p, g_aggh);   __nv_bfloat16* aggh = (__nv_bfloat16*)p;
    cudaGetSymbolAddress(&p, g_xh);     __nv_bfloat16* xh = (__nv_bfloat16*)p;
    cudaGetSymbolAddress(&p, g_bth);    __nv_bfloat16* bth = (__nv_bfloat16*)p;
    cudaGetSymbolAddress(&p, g_btl);    __nv_bfloat16* btl = (__nv_bfloat16*)p;
    cudaGetSymbolAddress(&p, g_deg);    int* deg = (int*)p;
    cudaGetSymbolAddress(&p, g_deginv); float* deginv = (float*)p;
    cudaGetSymbolAddress(&p, g_rowptr); int* rowptr = (int*)p;
    cudaGetSymbolAddress(&p, g_cursor); int* cursor = (int*)p;
    cudaGetSymbolAddress(&p, g_csr);    int* csr = (int*)p;
    cudaGetSymbolAddress(&p, g_blksum); int* blksum = (int*)p;
    cudaGetSymbolAddress(&p, g_blkoff); int* blkoff = (int*)p;
    cudaGetSymbolAddress(&p, g_colsum);   float* colsum = (float*)p;
    cudaGetSymbolAddress(&p, g_colsumsq); float* colsumsq = (float*)p;
    cudaGetSymbolAddress(&p, g_scale);  float* scale = (float*)p;
    cudaGetSymbolAddress(&p, g_shift);  float* shift = (float*)p;
    cudaGetSymbolAddress(&p, g_pool);   float* pool = (float*)p;

    static cudaStream_t s1 = nullptr;
    static cudaEvent_t evFork = nullptr, evXh = nullptr, evSide = nullptr;
    if (!s1) {
        cudaStreamCreateWithFlags(&s1, cudaStreamNonBlocking);
        cudaEventCreateWithFlags(&evFork, cudaEventDisableTiming);
        cudaEventCreateWithFlags(&evXh, cudaEventDisableTiming);
        cudaEventCreateWithFlags(&evSide, cudaEventDisableTiming);
        cudaFuncSetAttribute(k_mma<true>, cudaFuncAttributeMaxDynamicSharedMemorySize, SMEM_MMA);
        cudaFuncSetAttribute(k_mma<false>, cudaFuncAttributeMaxDynamicSharedMemorySize, SMEM_MMA);
    }

    auto bt_h = [&](int slot) { return bth + (size_t)slot * HDIM * HDIM; };
    auto bt_l = [&](int slot) { return btl + (size_t)slot * HDIM * HDIM; };

    const int agg_blocks = (N_NODES * 32 + 255) / 256;
    const dim3 gemm_grid((N_NODES + 127) / 128, HDIM / 128);
    const int norm_grid = (N_NODES * HDIM / 4 + 255) / 256;

    // ---- fork: CSR chain on stream 0, prep chain + res-GEMM on s1 ----
    cudaEventRecord(evFork, 0);
    cudaStreamWaitEvent(s1, evFork, 0);

    // stream 0: CSR build
    k_prep0<<<(N_NODES + 255) / 256, 256>>>((const int*)ei);
    k_degree<<<(N_EDGES + 255) / 256, 256>>>(ei, deg);
    k_scan_partial<<<NB, SB>>>(deg, blksum);
    k_scan_blk<<<1, 32>>>(blksum, blkoff, rowptr);
    k_scan_final<<<NB, SB>>>(deg, blkoff, rowptr, deginv);
    k_fillcsr<<<(N_EDGES + 255) / 256, 256>>>(ei, rowptr, cursor, csr);

    // stream s1: operand prep + residual GEMM
    k_split_x<<<(N_NODES * F_IN / 4 + 255) / 256, 256, 0, s1>>>((const float4*)x, xh);
    cudaEventRecord(evXh, s1);
    {
        PrepJobs j;
        j.W[0] = W[0][0]; j.K[0] = F_IN; j.OH[0] = bt_h(0); j.OL[0] = bt_l(0);
        j.W[1] = W[0][2]; j.K[1] = F_IN; j.OH[1] = bt_h(1); j.OL[1] = bt_l(1);
        j.W[2] = resW;    j.K[2] = F_IN; j.OH[2] = bt_h(2); j.OL[2] = bt_l(2);
        for (int b = 1; b < 4; b++) {
            int s0 = 3 + (b - 1) * 2;
            j.W[s0] = W[b][0]; j.K[s0] = HDIM; j.OH[s0] = bt_h(s0); j.OL[s0] = bt_l(s0);
            j.W[s0 + 1] = W[b][2]; j.K[s0 + 1] = HDIM; j.OH[s0 + 1] = bt_h(s0 + 1); j.OL[s0 + 1] = bt_l(s0 + 1);
        }
        k_prep_w_all<<<dim3(HDIM, 9), 256, 0, s1>>>(j);
    }
    {   // residual GEMM: (x @ resW + resb) -> hh/hl split (keeps weight-lo)
        GArgs a = {};
        a.pr[0] = { xh, bt_h(2), bt_l(2) };
        a.npair = 1; a.K = F_IN; a.bias = resb;
        a.CH = hh; a.CL = hl; a.outmode = 1;
        k_mma<true><<<gemm_grid, 256, SMEM_MMA, s1>>>(a);
    }
    cudaEventRecord(evSide, s1);

    // stream 0: layer-1 aggregation — overlaps res-GEMM
    cudaStreamWaitEvent(0, evXh, 0);
    k_agg<F_IN><<<agg_blocks, 256>>>(xh, rowptr, csr, deginv, aggh);
    cudaStreamWaitEvent(0, evSide, 0);

    // ---- block 1 ----
    {
        GArgs a = {};
        a.pr[0] = { aggh, bt_h(0), nullptr };
        a.pr[1] = { xh,   bt_h(1), nullptr };
        a.npair = 2; a.K = F_IN; a.bias = W[0][1];
        a.C = h2b; a.cs = colsum; a.cs2 = colsumsq; a.outmode = 0;
        k_mma<false><<<gemm_grid, 256, SMEM_MMA>>>(a);
    }
    k_bnfinal<<<1, 256>>>(colsum, colsumsq, W[0][3], W[0][4], scale, shift);
    k_norm<<<norm_grid, 256>>>(h2b, scale, shift, hh, hl);

    // ---- blocks 2..4 ----
    for (int b = 1; b < 4; b++) {
        int sl = 3 + (b - 1) * 2, sr = sl + 1;
        k_agg<HDIM><<<agg_blocks, 256>>>(hh, rowptr, csr, deginv, aggh);
        GArgs a = {};
        a.pr[0] = { aggh, bt_h(sl), nullptr };
        a.pr[1] = { hh,   bt_h(sr), nullptr };
        a.npair = 2; a.K = HDIM; a.bias = W[b][1];
        a.C = h2b; a.cs = colsum; a.cs2 = colsumsq; a.outmode = 0;
        k_mma<false><<<gemm_grid, 256, SMEM_MMA>>>(a);
        k_bnfinal<<<1, 256>>>(colsum, colsumsq, W[b][3], W[b][4], scale, shift);
        k_norm<<<norm_grid, 256>>>(h2b, scale, shift, hh, hl);
    }

    // ---- pooling + head ----
    k_pool<<<N_GRAPHS, 128>>>(hh, hl, bat, pool);
    k_final<<<N_GRAPHS / 8, 256>>>(pool, linW, linb, out);
}

// round 16
// speedup vs baseline: 1.3127x; 1.0665x over previous
#include <cuda_runtime.h>
#include <cuda_bf16.h>
#include <cstdint>

#define N_NODES 100000
#define N_EDGES 1600000
#define N_GRAPHS 256
#define F_IN 128
#define HDIM 256
#define EPS 1e-5f

#define SB 512
#define NB ((N_NODES + SB - 1) / SB)   // 196

// ========================== PTX helpers (sm_80-class only) ===================
__device__ __forceinline__ uint32_t smem_to_u32(const void* p) {
    uint32_t a;
    asm("{ .reg .u64 t; cvta.to.shared.u64 t, %1; cvt.u32.u64 %0, t; }" : "=r"(a) : "l"(p));
    return a;
}
__device__ __forceinline__ void cp16(uint32_t d, const void* s) {
    asm volatile("cp.async.cg.shared.global [%0], [%1], 16;" :: "r"(d), "l"(s));
}
__device__ __forceinline__ void cp_commit() { asm volatile("cp.async.commit_group;" ::: "memory"); }
template <int N> __device__ __forceinline__ void cp_wait() {
    asm volatile("cp.async.wait_group %0;" :: "n"(N) : "memory");
}
__device__ __forceinline__ void ldm_x4(uint32_t* d, uint32_t addr) {
    asm volatile("ldmatrix.sync.aligned.m8n8.x4.shared.b16 {%0,%1,%2,%3}, [%4];"
                 : "=r"(d[0]), "=r"(d[1]), "=r"(d[2]), "=r"(d[3]) : "r"(addr));
}
__device__ __forceinline__ void ldm_x2(uint32_t* d, uint32_t addr) {
    asm volatile("ldmatrix.sync.aligned.m8n8.x2.shared.b16 {%0,%1}, [%2];"
                 : "=r"(d[0]), "=r"(d[1]) : "r"(addr));
}
__device__ __forceinline__ void mma_bf16(float* c, const uint32_t* a, const uint32_t* b) {
    asm volatile("mma.sync.aligned.m16n8k16.row.col.f32.bf16.bf16.f32 "
                 "{%0,%1,%2,%3}, {%4,%5,%6,%7}, {%8,%9}, {%0,%1,%2,%3};"
                 : "+f"(c[0]), "+f"(c[1]), "+f"(c[2]), "+f"(c[3])
                 : "r"(a[0]), "r"(a[1]), "r"(a[2]), "r"(a[3]), "r"(b[0]), "r"(b[1]));
}

// ============================ scratch (static) ================================
// NOTE: buffer set/sizes/order preserved from the champion build — layout matters
// (R8/R9 showed deleting g_hl cost ~240us). g_hl stays allocated and written by
// the residual GEMM, but is no longer read in norm/pool (bf16-only residual).
__device__ __align__(256) float g_h2[(size_t)N_NODES * HDIM];
__device__ __align__(256) __nv_bfloat16 g_hh [(size_t)N_NODES * HDIM];
__device__ __align__(256) __nv_bfloat16 g_hl [(size_t)N_NODES * HDIM];
__device__ __align__(256) __nv_bfloat16 g_aggh[(size_t)N_NODES * HDIM];
__device__ __align__(256) __nv_bfloat16 g_xh[(size_t)N_NODES * F_IN];
__device__ __align__(256) __nv_bfloat16 g_bth[9][HDIM * HDIM];
__device__ __align__(256) __nv_bfloat16 g_btl[9][HDIM * HDIM];
__device__ int   g_deg[N_NODES];
__device__ float g_deginv[N_NODES];
__device__ int   g_rowptr[N_NODES + 1];
__device__ int   g_cursor[N_NODES];
__device__ int   g_csr[N_EDGES];
__device__ int   g_blksum[NB];
__device__ int   g_blkoff[NB];
__device__ float g_colsum[HDIM];
__device__ float g_colsumsq[HDIM];
__device__ float g_scale[HDIM];
__device__ float g_shift[HDIM];
__device__ float g_pool[N_GRAPHS * HDIM];
__device__ int   g_is64;

// =================== prologue: dtype detect + zero deg/cursor ================
__global__ void k_prep0(const int* __restrict__ ei32) {
    int i = blockIdx.x * 256 + threadIdx.x;
    if (i < N_NODES) { g_deg[i] = 0; g_cursor[i] = 0; }
    if (blockIdx.x == 0) {
        __shared__ int nz;
        if (threadIdx.x == 0) nz = 0;
        __syncthreads();
        int acc = 0;
#pragma unroll
        for (int q = 0; q < 4; q++) acc |= ei32[2 * (threadIdx.x * 4 + q) + 1];
        if (acc) atomicOr(&nz, 1);
        __syncthreads();
        if (threadIdx.x == 0) g_is64 = (nz == 0) ? 1 : 0;
    }
}
__device__ __forceinline__ long long load_idx(const void* p, long long i, int is64) {
    return is64 ? ((const long long*)p)[i] : (long long)((const int*)p)[i];
}
__global__ void k_degree(const void* __restrict__ ei, int* __restrict__ deg) {
    int e = blockIdx.x * blockDim.x + threadIdx.x;
    if (e >= N_EDGES) return;
    int dst = (int)load_idx(ei, (long long)N_EDGES + e, g_is64);
    atomicAdd(&deg[dst], 1);
}
__global__ void k_scan_partial(const int* __restrict__ deg, int* __restrict__ blksum) {
    __shared__ int sh[SB];
    int i = blockIdx.x * SB + threadIdx.x;
    sh[threadIdx.x] = (i < N_NODES) ? deg[i] : 0;
    __syncthreads();
    for (int o = SB / 2; o > 0; o >>= 1) {
        if (threadIdx.x < o) sh[threadIdx.x] += sh[threadIdx.x + o];
        __syncthreads();
    }
    if (threadIdx.x == 0) blksum[blockIdx.x] = sh[0];
}
__global__ void k_scan_blk(const int* __restrict__ blksum, int* __restrict__ blkoff,
                           int* __restrict__ rowptr) {
    if (threadIdx.x == 0) {
        int a = 0;
        for (int b = 0; b < NB; b++) { blkoff[b] = a; a += blksum[b]; }
        rowptr[N_NODES] = a;
    }
}
__global__ void k_scan_final(const int* __restrict__ deg, const int* __restrict__ blkoff,
                             int* __restrict__ rowptr, float* __restrict__ deginv) {
    __shared__ int sh[SB];
    int i = blockIdx.x * SB + threadIdx.x;
    int v = (i < N_NODES) ? deg[i] : 0;
    sh[threadIdx.x] = v;
    __syncthreads();
    for (int o = 1; o < SB; o <<= 1) {
        int t = (threadIdx.x >= o) ? sh[threadIdx.x - o] : 0;
        __syncthreads();
        sh[threadIdx.x] += t;
        __syncthreads();
    }
    if (i < N_NODES) {
        rowptr[i] = blkoff[blockIdx.x] + sh[threadIdx.x] - v;
        deginv[i] = 1.0f / (float)max(v, 1);
    }
}
__global__ void k_fillcsr(const void* __restrict__ ei, const int* __restrict__ rowptr,
                          int* __restrict__ cursor, int* __restrict__ csr) {
    int e = blockIdx.x * blockDim.x + threadIdx.x;
    if (e >= N_EDGES) return;
    int is64 = g_is64;
    int src = (int)load_idx(ei, e, is64);
    int dst = (int)load_idx(ei, (long long)N_EDGES + e, is64);
    int p = atomicAdd(&cursor[dst], 1);
    csr[rowptr[dst] + p] = src;
}

// ========== aggregation: CSR gather (16B vector loads) -> bf16 mean ==========
template <int F>
__global__ void __launch_bounds__(256) k_agg(
    const __nv_bfloat16* __restrict__ XH, const int* __restrict__ rowptr,
    const int* __restrict__ csr, const float* __restrict__ deginv,
    __nv_bfloat16* __restrict__ AH)
{
    if (blockIdx.x == 0) { g_colsum[threadIdx.x] = 0.f; g_colsumsq[threadIdx.x] = 0.f; }
    int node = (blockIdx.x * 256 + threadIdx.x) >> 5;
    int lane = threadIdx.x & 31;
    if (node >= N_NODES) return;
    int beg = rowptr[node], end = rowptr[node + 1];
    constexpr int E = F / 32;
    float acc[E];
#pragma unroll
    for (int t = 0; t < E; t++) acc[t] = 0.f;

    auto addrow = [&](int s) {
        if (E == 8) {
            uint4 u = __ldg((const uint4*)(XH + (size_t)s * F) + lane);
            const uint32_t w[4] = { u.x, u.y, u.z, u.w };
#pragma unroll
            for (int t = 0; t < 4; t++) {
                float2 f = __bfloat1622float2(*(const __nv_bfloat162*)&w[t]);
                acc[2 * t] += f.x; acc[2 * t + 1] += f.y;
            }
        } else {
            uint2 u = __ldg((const uint2*)(XH + (size_t)s * F) + lane);
            const uint32_t w[2] = { u.x, u.y };
#pragma unroll
            for (int t = 0; t < 2; t++) {
                float2 f = __bfloat1622float2(*(const __nv_bfloat162*)&w[t]);
                acc[2 * t] += f.x; acc[2 * t + 1] += f.y;
            }
        }
    };
    int e = beg;
    for (; e + 7 < end; e += 8) {
        int s0 = csr[e],     s1 = csr[e + 1], s2 = csr[e + 2], s3 = csr[e + 3];
        int s4 = csr[e + 4], s5 = csr[e + 5], s6 = csr[e + 6], s7 = csr[e + 7];
        addrow(s0); addrow(s1); addrow(s2); addrow(s3);
        addrow(s4); addrow(s5); addrow(s6); addrow(s7);
    }
    for (; e + 1 < end; e += 2) {
        int s0 = csr[e], s1 = csr[e + 1];
        addrow(s0); addrow(s1);
    }
    for (; e < end; e++) addrow(csr[e]);

    float inv = deginv[node];
    uint32_t w[E / 2];
#pragma unroll
    for (int t = 0; t < E / 2; t++) {
        __nv_bfloat162 h2 = __floats2bfloat162_rn(acc[2 * t] * inv, acc[2 * t + 1] * inv);
        w[t] = *(uint32_t*)&h2;
    }
    if (E == 8)
        *((uint4*)(AH + (size_t)node * F) + lane) = make_uint4(w[0], w[1], w[2], w[3]);
    else
        *((uint2*)(AH + (size_t)node * F) + lane) = make_uint2(w[0], w[1]);
}

// =================== x -> bf16 conversion ====================================
__global__ void __launch_bounds__(256) k_split_x(const float4* __restrict__ X,
                                                 __nv_bfloat16* __restrict__ XH) {
    size_t i = (size_t)blockIdx.x * 256 + threadIdx.x;
    float4 v = X[i];
    __nv_bfloat162 a = __floats2bfloat162_rn(v.x, v.y);
    __nv_bfloat162 b = __floats2bfloat162_rn(v.z, v.w);
    ((uint2*)XH)[i] = make_uint2(*(uint32_t*)&a, *(uint32_t*)&b);
}

// ============ all weight transposes+splits in ONE launch =====================
struct PrepJobs {
    const float* W[9]; int K[9];
    __nv_bfloat16* OH[9]; __nv_bfloat16* OL[9];
};
__global__ void k_prep_w_all(PrepJobs jobs) {
    int j = blockIdx.y;
    int k = blockIdx.x;
    if (k >= jobs.K[j]) return;
    int n = threadIdx.x;
    float v = jobs.W[j][(size_t)k * HDIM + n];
    __nv_bfloat16 hi = __float2bfloat16(v);
    float lo = v - __bfloat162float(hi);
    jobs.OH[j][(size_t)n * jobs.K[j] + k] = hi;
    jobs.OL[j][(size_t)n * jobs.K[j] + k] = __float2bfloat16(lo);
}

// ====================== mma.sync bf16 pair-structured GEMM ===================
// C = sum_p A_p @ (B0_p [+ B1_p])^T + bias ; USEB1 compile-time (residual keeps
// weight-lo; main layer GEMMs drop it — BN absorbs the column bias).
// outmode 0: C bf16 (pre-norm raw) + fused BN column stats (stats in fp32)
// outmode 1: bf16 hi/lo split output (CH/CL)
struct Pair { const __nv_bfloat16* A; const __nv_bfloat16* B0; const __nv_bfloat16* B1; };
struct GArgs {
    Pair pr[2]; int npair; int K; const float* bias;
    __nv_bfloat16* C; __nv_bfloat16* CH; __nv_bfloat16* CL;
    float* cs; float* cs2; int outmode;
};

#define LDS_STRIDE 72   // bf16 per smem row (64 data + 8 pad) = 144B
#define TBUF (128 * LDS_STRIDE)              // elems per tile buffer
#define SMEM_MMA (6 * TBUF * 2)              // bytes: 2-stage x (A + B0 + B1)

template <bool USEB1>
__global__ void __launch_bounds__(256) k_mma(GArgs ga) {
    extern __shared__ __align__(16) __nv_bfloat16 dynsmem[];
    __shared__ float s_sum[128], s_sq[128];

    const int tid = threadIdx.x;
    const int wid = tid >> 5, lane = tid & 31;
    const int wr = wid & 1, wc = wid >> 1;
    const int row0 = blockIdx.x * 128;
    const int col0 = blockIdx.y * 128;

    const uint32_t base = smem_to_u32(dynsmem);
    auto abase  = [&](int buf) { return base + (uint32_t)buf * (TBUF * 2); };
    auto b0base = [&](int buf) { return base + (uint32_t)(2 + buf) * (TBUF * 2); };
    auto b1base = [&](int buf) { return base + (uint32_t)(4 + buf) * (TBUF * 2); };

    const int K = ga.K;
    const int kpc = K >> 6;           // 64-wide chunks per pair
    const int nch = ga.npair * kpc;

    float acc[4][4][4];
#pragma unroll
    for (int mt = 0; mt < 4; mt++)
#pragma unroll
        for (int nt = 0; nt < 4; nt++)
#pragma unroll
            for (int q = 0; q < 4; q++) acc[mt][nt][q] = 0.f;

    const int a_r = lane & 15, a_c = lane >> 4;
    const int b_l = lane & 7, b_h = (lane >> 3) & 1;

    auto fill = [&](int buf, int ch) {
        int p = ch / kpc, kc = ch - p * kpc;
        const __nv_bfloat16* A  = ga.pr[p].A;
        const __nv_bfloat16* B0 = ga.pr[p].B0;
        const __nv_bfloat16* B1 = ga.pr[p].B1;
        uint32_t ab = abase(buf), b0b = b0base(buf), b1b = b1base(buf);
        int koff = kc * 64;
#pragma unroll
        for (int q = 0; q < 4; q++) {
            int i = tid + q * 256;            // 0..1023
            int r = i >> 3, pp = i & 7;
            int gr = row0 + r; if (gr > N_NODES - 1) gr = N_NODES - 1;
            uint32_t soff = r * (LDS_STRIDE * 2) + pp * 16;
            size_t goff = (size_t)(koff + pp * 8);
            cp16(ab  + soff, A  + ((size_t)gr * K + goff));
            cp16(b0b + soff, B0 + ((size_t)(col0 + r) * K + goff));
            if (USEB1)
                cp16(b1b + soff, B1 + ((size_t)(col0 + r) * K + goff));
        }
        cp_commit();
    };

    fill(0, 0);
    for (int c = 0; c < nch; c++) {
        const int buf = c & 1;
        if (c + 1 < nch) {
            fill(buf ^ 1, c + 1);
            cp_wait<1>();
        } else {
            cp_wait<0>();
        }
        __syncthreads();

        const uint32_t ab = abase(buf);
        const uint32_t bb[2] = { b0base(buf), b1base(buf) };
#pragma unroll
        for (int ks = 0; ks < 4; ks++) {
            uint32_t a[4][4];
#pragma unroll
            for (int mt = 0; mt < 4; mt++)
                ldm_x4(a[mt], ab + ((wr * 64 + mt * 16 + a_r) * LDS_STRIDE
                                    + ks * 16 + a_c * 8) * 2);
#pragma unroll
            for (int g = 0; g < (USEB1 ? 2 : 1); g++) {
                uint32_t b[4][2];
#pragma unroll
                for (int nt = 0; nt < 4; nt++)
                    ldm_x2(b[nt], bb[g] + ((wc * 32 + nt * 8 + b_l) * LDS_STRIDE
                                           + ks * 16 + b_h * 8) * 2);
#pragma unroll
                for (int mt = 0; mt < 4; mt++)
#pragma unroll
                    for (int nt = 0; nt < 4; nt++)
                        mma_bf16(acc[mt][nt], a[mt], b[nt]);
            }
        }
        __syncthreads();
    }

    // ---------------- epilogue ----------------
    if (ga.outmode == 0 && tid < 128) { s_sum[tid] = 0.f; s_sq[tid] = 0.f; }
    __syncthreads();

    const int er = lane >> 2;
    const int ec = (lane & 3) * 2;
#pragma unroll
    for (int nt = 0; nt < 4; nt++) {
        const int lcol = wc * 32 + nt * 8 + ec;
        const int col = col0 + lcol;
        const float b0 = ga.bias[col], b1 = ga.bias[col + 1];
        float ls0 = 0.f, ls1 = 0.f, lq0 = 0.f, lq1 = 0.f;
#pragma unroll
        for (int mt = 0; mt < 4; mt++) {
#pragma unroll
            for (int half = 0; half < 2; half++) {
                int row = row0 + wr * 64 + mt * 16 + er + half * 8;
                if (row >= N_NODES) continue;
                float v0 = acc[mt][nt][half * 2 + 0] + b0;
                float v1 = acc[mt][nt][half * 2 + 1] + b1;
                if (ga.outmode == 0) {
                    *(__nv_bfloat162*)(ga.C + (size_t)row * HDIM + col) =
                        __floats2bfloat162_rn(v0, v1);
                    ls0 += v0; ls1 += v1;
                    lq0 = fmaf(v0, v0, lq0); lq1 = fmaf(v1, v1, lq1);
                } else {
                    __nv_bfloat16 h0 = __float2bfloat16(v0), h1 = __float2bfloat16(v1);
                    *(__nv_bfloat162*)(ga.CH + (size_t)row * HDIM + col) =
                        __nv_bfloat162(h0, h1);
                    *(__nv_bfloat162*)(ga.CL + (size_t)row * HDIM + col) =
                        __nv_bfloat162(__float2bfloat16(v0 - __bfloat162float(h0)),
                                       __float2bfloat16(v1 - __bfloat162float(h1)));
                }
            }
        }
        if (ga.outmode == 0) {
            atomicAdd(&s_sum[lcol], ls0);     atomicAdd(&s_sum[lcol + 1], ls1);
            atomicAdd(&s_sq[lcol], lq0);      atomicAdd(&s_sq[lcol + 1], lq1);
        }
    }
    if (ga.outmode == 0) {
        __syncthreads();
        if (tid < 128) {
            atomicAdd(&ga.cs[col0 + tid], s_sum[tid]);
            atomicAdd(&ga.cs2[col0 + tid], s_sq[tid]);
        }
    }
}

// ============================ BN finalize / norm =============================
__global__ void k_bnfinal(const float* __restrict__ cs, const float* __restrict__ cs2,
                          const float* __restrict__ gamma, const float* __restrict__ beta,
                          float* __restrict__ scale, float* __restrict__ shift) {
    int j = threadIdx.x;
    const float invN = 1.0f / (float)N_NODES;
    float mu = cs[j] * invN;
    float var = cs2[j] * invN - mu * mu;
    float sc = gamma[j] * rsqrtf(var + EPS);
    scale[j] = sc;
    shift[j] = beta[j] - mu * sc;
}
// h_new = relu(raw*scale+shift) + hh ; 16B vectorized, hh-only residual
__global__ void __launch_bounds__(256) k_norm(
    const __nv_bfloat16* __restrict__ RAW, const float* __restrict__ scale,
    const float* __restrict__ shift, __nv_bfloat16* __restrict__ HH)
{
    size_t i = (size_t)blockIdx.x * 256 + threadIdx.x;   // over N*H/8 uint4s
    int j = (int)((i & 31) << 3);                        // column base (8 cols)
    uint4 rw = ((const uint4*)RAW)[i];
    uint4 hw = ((const uint4*)HH)[i];
    const uint32_t* rwp = &rw.x;
    const uint32_t* hwp = &hw.x;
    uint32_t ow[4];
#pragma unroll
    for (int t = 0; t < 4; t++) {
        float2 rv = __bfloat1622float2(*(const __nv_bfloat162*)&rwp[t]);
        float2 fh = __bfloat1622float2(*(const __nv_bfloat162*)&hwp[t]);
        float2 sc = *(const float2*)(scale + j + 2 * t);
        float2 sh = *(const float2*)(shift + j + 2 * t);
        float o0 = fmaxf(fmaf(rv.x, sc.x, sh.x), 0.f) + fh.x;
        float o1 = fmaxf(fmaf(rv.y, sc.y, sh.y), 0.f) + fh.y;
        __nv_bfloat162 o = __floats2bfloat162_rn(o0, o1);
        ow[t] = *(uint32_t*)&o;
    }
    ((uint4*)HH)[i] = make_uint4(ow[0], ow[1], ow[2], ow[3]);
}

// ============================ pooling + head =================================
__device__ __forceinline__ int lower_bound_batch(const void* batch, long long val, int is64) {
    int lo = 0, hi = N_NODES;
    while (lo < hi) {
        int mid = (lo + hi) >> 1;
        long long b = is64 ? ((const long long*)batch)[mid]
                           : (long long)((const int*)batch)[mid];
        if (b < val) lo = mid + 1; else hi = mid;
    }
    return lo;
}
__global__ void k_pool(const __nv_bfloat16* __restrict__ HH,
                       const void* __restrict__ batch, float* __restrict__ pool) {
    int g = blockIdx.x;
    __shared__ int slo, shi;
    if (threadIdx.x == 0) {
        int is64 = g_is64;
        slo = lower_bound_batch(batch, g, is64);
        shi = lower_bound_batch(batch, g + 1, is64);
    }
    __syncthreads();
    int j = threadIdx.x;           // 0..127 -> columns 2j, 2j+1
    float s0 = 0.f, s1 = 0.f;
    for (int n = slo; n < shi; n++) {
        float2 fh = __bfloat1622float2(((const __nv_bfloat162*)HH)[(size_t)n * (HDIM / 2) + j]);
        s0 += fh.x; s1 += fh.y;
    }
    float inv = 1.0f / (float)max(shi - slo, 1);
    pool[g * HDIM + 2 * j]     = s0 * inv;
    pool[g * HDIM + 2 * j + 1] = s1 * inv;
}
__global__ void k_final(const float* __restrict__ pool, const float* __restrict__ linW,
                        const float* __restrict__ linb, float* __restrict__ out) {
    int g = blockIdx.x * 8 + (threadIdx.x >> 5);
    int lane = threadIdx.x & 31;
    if (g >= N_GRAPHS) return;
    float s = 0.f;
#pragma unroll
    for (int q = 0; q < 8; q++) {
        int k = lane + q * 32;
        s = fmaf(pool[g * HDIM + k], linW[k], s);
    }
#pragma unroll
    for (int o = 16; o > 0; o >>= 1) s += __shfl_xor_sync(0xFFFFFFFFu, s, o);
    if (lane == 0) out[g] = s + linb[0];
}

// ============================ host orchestration ============================
extern "C" void kernel_launch(void* const* d_in, const int* in_sizes, int n_in,
                              void* d_out, int out_size) {
    const float* x   = (const float*)d_in[0];
    const void*  ei  = d_in[1];
    const void*  bat = d_in[2];
    const float* W[4][5];
    for (int b = 0; b < 4; b++)
        for (int k = 0; k < 5; k++)
            W[b][k] = (const float*)d_in[3 + b * 5 + k];
    const float* resW = (const float*)d_in[23];
    const float* resb = (const float*)d_in[24];
    const float* linW = (const float*)d_in[25];
    const float* linb = (const float*)d_in[26];
    float* out = (float*)d_out;

    void* p;
    cudaGetSymbolAddress(&p, g_h2);     __nv_bfloat16* h2b = (__nv_bfloat16*)p;
    cudaGetSymbolAddress(&p, g_hh);     __nv_bfloat16* hh = (__nv_bfloat16*)p;
    cudaGetSymbolAddress(&p, g_hl);     __nv_bfloat16* hl = (__nv_bfloat16*)p;
    cudaGetSymbolAddress(&p, g_aggh);   __nv_bfloat16* aggh = (__nv_bfloat16*)p;
    cudaGetSymbolAddress(&p, g_xh);     __nv_bfloat16* xh = (__nv_bfloat16*)p;
    cudaGetSymbolAddress(&p, g_bth);    __nv_bfloat16* bth = (__nv_bfloat16*)p;
    cudaGetSymbolAddress(&p, g_btl);    __nv_bfloat16* btl = (__nv_bfloat16*)p;
    cudaGetSymbolAddress(&p, g_deg);    int* deg = (int*)p;
    cudaGetSymbolAddress(&p, g_deginv); float* deginv = (float*)p;
    cudaGetSymbolAddress(&p, g_rowptr); int* rowptr = (int*)p;
    cudaGetSymbolAddress(&p, g_cursor); int* cursor = (int*)p;
    cudaGetSymbolAddress(&p, g_csr);    int* csr = (int*)p;
    cudaGetSymbolAddress(&p, g_blksum); int* blksum = (int*)p;
    cudaGetSymbolAddress(&p, g_blkoff); int* blkoff = (int*)p;
    cudaGetSymbolAddress(&p, g_colsum);   float* colsum = (float*)p;
    cudaGetSymbolAddress(&p, g_colsumsq); float* colsumsq = (float*)p;
    cudaGetSymbolAddress(&p, g_scale);  float* scale = (float*)p;
    cudaGetSymbolAddress(&p, g_shift);  float* shift = (float*)p;
    cudaGetSymbolAddress(&p, g_pool);   float* pool = (float*)p;

    static cudaStream_t s1 = nullptr;
    static cudaEvent_t evFork = nullptr, evXh = nullptr, evSide = nullptr;
    if (!s1) {
        cudaStreamCreateWithFlags(&s1, cudaStreamNonBlocking);
        cudaEventCreateWithFlags(&evFork, cudaEventDisableTiming);
        cudaEventCreateWithFlags(&evXh, cudaEventDisableTiming);
        cudaEventCreateWithFlags(&evSide, cudaEventDisableTiming);
        cudaFuncSetAttribute(k_mma<true>, cudaFuncAttributeMaxDynamicSharedMemorySize, SMEM_MMA);
        cudaFuncSetAttribute(k_mma<false>, cudaFuncAttributeMaxDynamicSharedMemorySize, SMEM_MMA);
    }

    auto bt_h = [&](int slot) { return bth + (size_t)slot * HDIM * HDIM; };
    auto bt_l = [&](int slot) { return btl + (size_t)slot * HDIM * HDIM; };

    const int agg_blocks = (N_NODES * 32 + 255) / 256;
    const dim3 gemm_grid((N_NODES + 127) / 128, HDIM / 128);
    const int norm_grid = (N_NODES * HDIM / 8 + 255) / 256;

    // ---- fork: CSR chain on stream 0, prep chain + res-GEMM on s1 ----
    cudaEventRecord(evFork, 0);
    cudaStreamWaitEvent(s1, evFork, 0);

    // stream 0: CSR build
    k_prep0<<<(N_NODES + 255) / 256, 256>>>((const int*)ei);
    k_degree<<<(N_EDGES + 255) / 256, 256>>>(ei, deg);
    k_scan_partial<<<NB, SB>>>(deg, blksum);
    k_scan_blk<<<1, 32>>>(blksum, blkoff, rowptr);
    k_scan_final<<<NB, SB>>>(deg, blkoff, rowptr, deginv);
    k_fillcsr<<<(N_EDGES + 255) / 256, 256>>>(ei, rowptr, cursor, csr);

    // stream s1: operand prep + residual GEMM
    k_split_x<<<(N_NODES * F_IN / 4 + 255) / 256, 256, 0, s1>>>((const float4*)x, xh);
    cudaEventRecord(evXh, s1);
    {
        PrepJobs j;
        j.W[0] = W[0][0]; j.K[0] = F_IN; j.OH[0] = bt_h(0); j.OL[0] = bt_l(0);
        j.W[1] = W[0][2]; j.K[1] = F_IN; j.OH[1] = bt_h(1); j.OL[1] = bt_l(1);
        j.W[2] = resW;    j.K[2] = F_IN; j.OH[2] = bt_h(2); j.OL[2] = bt_l(2);
        for (int b = 1; b < 4; b++) {
            int s0 = 3 + (b - 1) * 2;
            j.W[s0] = W[b][0]; j.K[s0] = HDIM; j.OH[s0] = bt_h(s0); j.OL[s0] = bt_l(s0);
            j.W[s0 + 1] = W[b][2]; j.K[s0 + 1] = HDIM; j.OH[s0 + 1] = bt_h(s0 + 1); j.OL[s0 + 1] = bt_l(s0 + 1);
        }
        k_prep_w_all<<<dim3(HDIM, 9), 256, 0, s1>>>(j);
    }
    {   // residual GEMM: (x @ resW + resb) -> hh/hl split (keeps weight-lo)
        GArgs a = {};
        a.pr[0] = { xh, bt_h(2), bt_l(2) };
        a.npair = 1; a.K = F_IN; a.bias = resb;
        a.CH = hh; a.CL = hl; a.outmode = 1;
        k_mma<true><<<gemm_grid, 256, SMEM_MMA, s1>>>(a);
    }
    cudaEventRecord(evSide, s1);

    // stream 0: layer-1 aggregation — overlaps res-GEMM
    cudaStreamWaitEvent(0, evXh, 0);
    k_agg<F_IN><<<agg_blocks, 256>>>(xh, rowptr, csr, deginv, aggh);
    cudaStreamWaitEvent(0, evSide, 0);

    // ---- block 1 ----
    {
        GArgs a = {};
        a.pr[0] = { aggh, bt_h(0), nullptr };
        a.pr[1] = { xh,   bt_h(1), nullptr };
        a.npair = 2; a.K = F_IN; a.bias = W[0][1];
        a.C = h2b; a.cs = colsum; a.cs2 = colsumsq; a.outmode = 0;
        k_mma<false><<<gemm_grid, 256, SMEM_MMA>>>(a);
    }
    k_bnfinal<<<1, 256>>>(colsum, colsumsq, W[0][3], W[0][4], scale, shift);
    k_norm<<<norm_grid, 256>>>(h2b, scale, shift, hh);

    // ---- blocks 2..4 ----
    for (int b = 1; b < 4; b++) {
        int sl = 3 + (b - 1) * 2, sr = sl + 1;
        k_agg<HDIM><<<agg_blocks, 256>>>(hh, rowptr, csr, deginv, aggh);
        GArgs a = {};
        a.pr[0] = { aggh, bt_h(sl), nullptr };
        a.pr[1] = { hh,   bt_h(sr), nullptr };
        a.npair = 2; a.K = HDIM; a.bias = W[b][1];
        a.C = h2b; a.cs = colsum; a.cs2 = colsumsq; a.outmode = 0;
        k_mma<false><<<gemm_grid, 256, SMEM_MMA>>>(a);
        k_bnfinal<<<1, 256>>>(colsum, colsumsq, W[b][3], W[b][4], scale, shift);
        k_norm<<<norm_grid, 256>>>(h2b, scale, shift, hh);
    }

    // ---- pooling + head ----
    k_pool<<<N_GRAPHS, 128>>>(hh, bat, pool);
    k_final<<<N_GRAPHS / 8, 256>>>(pool, linW, linb, out);
}

// round 17
// speedup vs baseline: 1.3473x; 1.0264x over previous
#include <cuda_runtime.h>
#include <cuda_bf16.h>
#include <cstdint>

#define N_NODES 100000
#define N_EDGES 1600000
#define N_GRAPHS 256
#define F_IN 128
#define HDIM 256
#define EPS 1e-5f

#define SB 512
#define NB ((N_NODES + SB - 1) / SB)   // 196

// ========================== PTX helpers (sm_80-class only) ===================
__device__ __forceinline__ uint32_t smem_to_u32(const void* p) {
    uint32_t a;
    asm("{ .reg .u64 t; cvta.to.shared.u64 t, %1; cvt.u32.u64 %0, t; }" : "=r"(a) : "l"(p));
    return a;
}
__device__ __forceinline__ void cp16(uint32_t d, const void* s) {
    asm volatile("cp.async.cg.shared.global [%0], [%1], 16;" :: "r"(d), "l"(s));
}
__device__ __forceinline__ void cp_commit() { asm volatile("cp.async.commit_group;" ::: "memory"); }
template <int N> __device__ __forceinline__ void cp_wait() {
    asm volatile("cp.async.wait_group %0;" :: "n"(N) : "memory");
}
__device__ __forceinline__ void ldm_x4(uint32_t* d, uint32_t addr) {
    asm volatile("ldmatrix.sync.aligned.m8n8.x4.shared.b16 {%0,%1,%2,%3}, [%4];"
                 : "=r"(d[0]), "=r"(d[1]), "=r"(d[2]), "=r"(d[3]) : "r"(addr));
}
__device__ __forceinline__ void ldm_x2(uint32_t* d, uint32_t addr) {
    asm volatile("ldmatrix.sync.aligned.m8n8.x2.shared.b16 {%0,%1}, [%2];"
                 : "=r"(d[0]), "=r"(d[1]) : "r"(addr));
}
__device__ __forceinline__ void mma_bf16(float* c, const uint32_t* a, const uint32_t* b) {
    asm volatile("mma.sync.aligned.m16n8k16.row.col.f32.bf16.bf16.f32 "
                 "{%0,%1,%2,%3}, {%4,%5,%6,%7}, {%8,%9}, {%0,%1,%2,%3};"
                 : "+f"(c[0]), "+f"(c[1]), "+f"(c[2]), "+f"(c[3])
                 : "r"(a[0]), "r"(a[1]), "r"(a[2]), "r"(a[3]), "r"(b[0]), "r"(b[1]));
}

// ============================ scratch (static) ================================
// NOTE: buffer set/sizes/order preserved from the champion build — layout matters
// (R8/R9 showed deleting g_hl cost ~240us). g_hl stays allocated and written by
// the residual GEMM, but is no longer read (bf16-only residual).
__device__ __align__(256) float g_h2[(size_t)N_NODES * HDIM];
__device__ __align__(256) __nv_bfloat16 g_hh [(size_t)N_NODES * HDIM];
__device__ __align__(256) __nv_bfloat16 g_hl [(size_t)N_NODES * HDIM];
__device__ __align__(256) __nv_bfloat16 g_aggh[(size_t)N_NODES * HDIM];
__device__ __align__(256) __nv_bfloat16 g_xh[(size_t)N_NODES * F_IN];
__device__ __align__(256) __nv_bfloat16 g_bth[9][HDIM * HDIM];
__device__ __align__(256) __nv_bfloat16 g_btl[9][HDIM * HDIM];
__device__ int   g_deg[N_NODES];
__device__ float g_deginv[N_NODES];
__device__ int   g_rowptr[N_NODES + 1];
__device__ int   g_cursor[N_NODES];
__device__ int   g_csr[N_EDGES];
__device__ int   g_blksum[NB];
__device__ int   g_blkoff[NB];
__device__ float g_colsum[HDIM];
__device__ float g_colsumsq[HDIM];
__device__ float g_scale[HDIM];
__device__ float g_shift[HDIM];
__device__ float g_pool[N_GRAPHS * HDIM];
__device__ int   g_is64;
__device__ int   g_ctr;

// =================== prologue: dtype detect + zero deg/cursor ================
__global__ void k_prep0(const int* __restrict__ ei32) {
    int i = blockIdx.x * 256 + threadIdx.x;
    if (i < N_NODES) { g_deg[i] = 0; g_cursor[i] = 0; }
    if (blockIdx.x == 0) {
        __shared__ int nz;
        if (threadIdx.x == 0) nz = 0;
        __syncthreads();
        int acc = 0;
#pragma unroll
        for (int q = 0; q < 4; q++) acc |= ei32[2 * (threadIdx.x * 4 + q) + 1];
        if (acc) atomicOr(&nz, 1);
        __syncthreads();
        if (threadIdx.x == 0) g_is64 = (nz == 0) ? 1 : 0;
    }
}
// 2 edges per thread, vectorized dst loads
__global__ void k_degree(const void* __restrict__ ei, int* __restrict__ deg) {
    int t = blockIdx.x * blockDim.x + threadIdx.x;   // 0 .. N_EDGES/2-1
    if (t >= N_EDGES / 2) return;
    int d0, d1;
    if (g_is64) {
        longlong2 v = ((const longlong2*)((const long long*)ei + N_EDGES))[t];
        d0 = (int)v.x; d1 = (int)v.y;
    } else {
        int2 v = ((const int2*)((const int*)ei + N_EDGES))[t];
        d0 = v.x; d1 = v.y;
    }
    atomicAdd(&deg[d0], 1);
    atomicAdd(&deg[d1], 1);
}
__global__ void k_scan_partial(const int* __restrict__ deg, int* __restrict__ blksum) {
    __shared__ int sh[SB];
    int i = blockIdx.x * SB + threadIdx.x;
    sh[threadIdx.x] = (i < N_NODES) ? deg[i] : 0;
    __syncthreads();
    for (int o = SB / 2; o > 0; o >>= 1) {
        if (threadIdx.x < o) sh[threadIdx.x] += sh[threadIdx.x + o];
        __syncthreads();
    }
    if (threadIdx.x == 0) blksum[blockIdx.x] = sh[0];
}
__global__ void k_scan_blk(const int* __restrict__ blksum, int* __restrict__ blkoff,
                           int* __restrict__ rowptr) {
    if (threadIdx.x == 0) {
        int a = 0;
        for (int b = 0; b < NB; b++) { blkoff[b] = a; a += blksum[b]; }
        rowptr[N_NODES] = a;
    }
}
__global__ void k_scan_final(const int* __restrict__ deg, const int* __restrict__ blkoff,
                             int* __restrict__ rowptr, float* __restrict__ deginv) {
    __shared__ int sh[SB];
    int i = blockIdx.x * SB + threadIdx.x;
    int v = (i < N_NODES) ? deg[i] : 0;
    sh[threadIdx.x] = v;
    __syncthreads();
    for (int o = 1; o < SB; o <<= 1) {
        int t = (threadIdx.x >= o) ? sh[threadIdx.x - o] : 0;
        __syncthreads();
        sh[threadIdx.x] += t;
        __syncthreads();
    }
    if (i < N_NODES) {
        rowptr[i] = blkoff[blockIdx.x] + sh[threadIdx.x] - v;
        deginv[i] = 1.0f / (float)max(v, 1);
    }
}
// 2 edges per thread, vectorized src/dst loads
__global__ void k_fillcsr(const void* __restrict__ ei, const int* __restrict__ rowptr,
                          int* __restrict__ cursor, int* __restrict__ csr) {
    int t = blockIdx.x * blockDim.x + threadIdx.x;
    if (t >= N_EDGES / 2) return;
    int s0, s1, d0, d1;
    if (g_is64) {
        longlong2 sv = ((const longlong2*)ei)[t];
        longlong2 dv = ((const longlong2*)((const long long*)ei + N_EDGES))[t];
        s0 = (int)sv.x; s1 = (int)sv.y; d0 = (int)dv.x; d1 = (int)dv.y;
    } else {
        int2 sv = ((const int2*)ei)[t];
        int2 dv = ((const int2*)((const int*)ei + N_EDGES))[t];
        s0 = sv.x; s1 = sv.y; d0 = dv.x; d1 = dv.y;
    }
    int p0 = atomicAdd(&cursor[d0], 1);
    csr[rowptr[d0] + p0] = s0;
    int p1 = atomicAdd(&cursor[d1], 1);
    csr[rowptr[d1] + p1] = s1;
}

// ========== aggregation: CSR gather (16B vector loads) -> bf16 mean ==========
// Block 0 also zeroes BN stat accumulators + GEMM completion counter.
template <int F>
__global__ void __launch_bounds__(256) k_agg(
    const __nv_bfloat16* __restrict__ XH, const int* __restrict__ rowptr,
    const int* __restrict__ csr, const float* __restrict__ deginv,
    __nv_bfloat16* __restrict__ AH)
{
    if (blockIdx.x == 0) {
        g_colsum[threadIdx.x] = 0.f; g_colsumsq[threadIdx.x] = 0.f;
        if (threadIdx.x == 0) g_ctr = 0;
    }
    int node = (blockIdx.x * 256 + threadIdx.x) >> 5;
    int lane = threadIdx.x & 31;
    if (node >= N_NODES) return;
    int beg = rowptr[node], end = rowptr[node + 1];
    constexpr int E = F / 32;
    float acc[E];
#pragma unroll
    for (int t = 0; t < E; t++) acc[t] = 0.f;

    auto addrow = [&](int s) {
        if (E == 8) {
            uint4 u = __ldg((const uint4*)(XH + (size_t)s * F) + lane);
            const uint32_t w[4] = { u.x, u.y, u.z, u.w };
#pragma unroll
            for (int t = 0; t < 4; t++) {
                float2 f = __bfloat1622float2(*(const __nv_bfloat162*)&w[t]);
                acc[2 * t] += f.x; acc[2 * t + 1] += f.y;
            }
        } else {
            uint2 u = __ldg((const uint2*)(XH + (size_t)s * F) + lane);
            const uint32_t w[2] = { u.x, u.y };
#pragma unroll
            for (int t = 0; t < 2; t++) {
                float2 f = __bfloat1622float2(*(const __nv_bfloat162*)&w[t]);
                acc[2 * t] += f.x; acc[2 * t + 1] += f.y;
            }
        }
    };
    int e = beg;
    for (; e + 7 < end; e += 8) {
        int s0 = csr[e],     s1 = csr[e + 1], s2 = csr[e + 2], s3 = csr[e + 3];
        int s4 = csr[e + 4], s5 = csr[e + 5], s6 = csr[e + 6], s7 = csr[e + 7];
        addrow(s0); addrow(s1); addrow(s2); addrow(s3);
        addrow(s4); addrow(s5); addrow(s6); addrow(s7);
    }
    for (; e + 1 < end; e += 2) {
        int s0 = csr[e], s1 = csr[e + 1];
        addrow(s0); addrow(s1);
    }
    for (; e < end; e++) addrow(csr[e]);

    float inv = deginv[node];
    uint32_t w[E / 2];
#pragma unroll
    for (int t = 0; t < E / 2; t++) {
        __nv_bfloat162 h2 = __floats2bfloat162_rn(acc[2 * t] * inv, acc[2 * t + 1] * inv);
        w[t] = *(uint32_t*)&h2;
    }
    if (E == 8)
        *((uint4*)(AH + (size_t)node * F) + lane) = make_uint4(w[0], w[1], w[2], w[3]);
    else
        *((uint2*)(AH + (size_t)node * F) + lane) = make_uint2(w[0], w[1]);
}

// =================== x -> bf16 conversion ====================================
__global__ void __launch_bounds__(256) k_split_x(const float4* __restrict__ X,
                                                 __nv_bfloat16* __restrict__ XH) {
    size_t i = (size_t)blockIdx.x * 256 + threadIdx.x;
    float4 v = X[i];
    __nv_bfloat162 a = __floats2bfloat162_rn(v.x, v.y);
    __nv_bfloat162 b = __floats2bfloat162_rn(v.z, v.w);
    ((uint2*)XH)[i] = make_uint2(*(uint32_t*)&a, *(uint32_t*)&b);
}

// ============ all weight transposes+splits in ONE launch =====================
struct PrepJobs {
    const float* W[9]; int K[9];
    __nv_bfloat16* OH[9]; __nv_bfloat16* OL[9];
};
__global__ void k_prep_w_all(PrepJobs jobs) {
    int j = blockIdx.y;
    int k = blockIdx.x;
    if (k >= jobs.K[j]) return;
    int n = threadIdx.x;
    float v = jobs.W[j][(size_t)k * HDIM + n];
    __nv_bfloat16 hi = __float2bfloat16(v);
    float lo = v - __bfloat162float(hi);
    jobs.OH[j][(size_t)n * jobs.K[j] + k] = hi;
    jobs.OL[j][(size_t)n * jobs.K[j] + k] = __float2bfloat16(lo);
}

// ====================== mma.sync bf16 pair-structured GEMM ===================
// C = sum_p A_p @ (B0_p [+ B1_p])^T + bias ; USEB1 compile-time.
// outmode 0: C bf16 + fused BN column stats; LAST CTA (ticket) computes
//            scale/shift from gamma/beta (replaces the k_bnfinal launch).
// outmode 1: bf16 hi/lo split output (CH/CL)
struct Pair { const __nv_bfloat16* A; const __nv_bfloat16* B0; const __nv_bfloat16* B1; };
struct GArgs {
    Pair pr[2]; int npair; int K; const float* bias;
    __nv_bfloat16* C; __nv_bfloat16* CH; __nv_bfloat16* CL;
    float* cs; float* cs2; int outmode;
    const float* gamma; const float* beta; float* scale; float* shift;
};

#define LDS_STRIDE 72   // bf16 per smem row (64 data + 8 pad) = 144B
#define TBUF (128 * LDS_STRIDE)              // elems per tile buffer
#define SMEM_MMA (6 * TBUF * 2)              // bytes: 2-stage x (A + B0 + B1)
#define GEMM_CTAS (((N_NODES + 127) / 128) * (HDIM / 128))   // 1564

template <bool USEB1>
__global__ void __launch_bounds__(256) k_mma(GArgs ga) {
    extern __shared__ __align__(16) __nv_bfloat16 dynsmem[];
    __shared__ float s_sum[128], s_sq[128];
    __shared__ int s_last;

    const int tid = threadIdx.x;
    const int wid = tid >> 5, lane = tid & 31;
    const int wr = wid & 1, wc = wid >> 1;
    const int row0 = blockIdx.x * 128;
    const int col0 = blockIdx.y * 128;

    const uint32_t base = smem_to_u32(dynsmem);
    auto abase  = [&](int buf) { return base + (uint32_t)buf * (TBUF * 2); };
    auto b0base = [&](int buf) { return base + (uint32_t)(2 + buf) * (TBUF * 2); };
    auto b1base = [&](int buf) { return base + (uint32_t)(4 + buf) * (TBUF * 2); };

    const int K = ga.K;
    const int kpc = K >> 6;           // 64-wide chunks per pair
    const int nch = ga.npair * kpc;

    float acc[4][4][4];
#pragma unroll
    for (int mt = 0; mt < 4; mt++)
#pragma unroll
        for (int nt = 0; nt < 4; nt++)
#pragma unroll
            for (int q = 0; q < 4; q++) acc[mt][nt][q] = 0.f;

    const int a_r = lane & 15, a_c = lane >> 4;
    const int b_l = lane & 7, b_h = (lane >> 3) & 1;

    auto fill = [&](int buf, int ch) {
        int p = ch / kpc, kc = ch - p * kpc;
        const __nv_bfloat16* A  = ga.pr[p].A;
        const __nv_bfloat16* B0 = ga.pr[p].B0;
        const __nv_bfloat16* B1 = ga.pr[p].B1;
        uint32_t ab = abase(buf), b0b = b0base(buf), b1b = b1base(buf);
        int koff = kc * 64;
#pragma unroll
        for (int q = 0; q < 4; q++) {
            int i = tid + q * 256;            // 0..1023
            int r = i >> 3, pp = i & 7;
            int gr = row0 + r; if (gr > N_NODES - 1) gr = N_NODES - 1;
            uint32_t soff = r * (LDS_STRIDE * 2) + pp * 16;
            size_t goff = (size_t)(koff + pp * 8);
            cp16(ab  + soff, A  + ((size_t)gr * K + goff));
            cp16(b0b + soff, B0 + ((size_t)(col0 + r) * K + goff));
            if (USEB1)
                cp16(b1b + soff, B1 + ((size_t)(col0 + r) * K + goff));
        }
        cp_commit();
    };

    fill(0, 0);
    for (int c = 0; c < nch; c++) {
        const int buf = c & 1;
        if (c + 1 < nch) {
            fill(buf ^ 1, c + 1);
            cp_wait<1>();
        } else {
            cp_wait<0>();
        }
        __syncthreads();

        const uint32_t ab = abase(buf);
        const uint32_t bb[2] = { b0base(buf), b1base(buf) };
#pragma unroll
        for (int ks = 0; ks < 4; ks++) {
            uint32_t a[4][4];
#pragma unroll
            for (int mt = 0; mt < 4; mt++)
                ldm_x4(a[mt], ab + ((wr * 64 + mt * 16 + a_r) * LDS_STRIDE
                                    + ks * 16 + a_c * 8) * 2);
#pragma unroll
            for (int g = 0; g < (USEB1 ? 2 : 1); g++) {
                uint32_t b[4][2];
#pragma unroll
                for (int nt = 0; nt < 4; nt++)
                    ldm_x2(b[nt], bb[g] + ((wc * 32 + nt * 8 + b_l) * LDS_STRIDE
                                           + ks * 16 + b_h * 8) * 2);
#pragma unroll
                for (int mt = 0; mt < 4; mt++)
#pragma unroll
                    for (int nt = 0; nt < 4; nt++)
                        mma_bf16(acc[mt][nt], a[mt], b[nt]);
            }
        }
        __syncthreads();
    }

    // ---------------- epilogue ----------------
    if (ga.outmode == 0 && tid < 128) { s_sum[tid] = 0.f; s_sq[tid] = 0.f; }
    __syncthreads();

    const int er = lane >> 2;
    const int ec = (lane & 3) * 2;
#pragma unroll
    for (int nt = 0; nt < 4; nt++) {
        const int lcol = wc * 32 + nt * 8 + ec;
        const int col = col0 + lcol;
        const float b0 = ga.bias[col], b1 = ga.bias[col + 1];
        float ls0 = 0.f, ls1 = 0.f, lq0 = 0.f, lq1 = 0.f;
#pragma unroll
        for (int mt = 0; mt < 4; mt++) {
#pragma unroll
            for (int half = 0; half < 2; half++) {
                int row = row0 + wr * 64 + mt * 16 + er + half * 8;
                if (row >= N_NODES) continue;
                float v0 = acc[mt][nt][half * 2 + 0] + b0;
                float v1 = acc[mt][nt][half * 2 + 1] + b1;
                if (ga.outmode == 0) {
                    *(__nv_bfloat162*)(ga.C + (size_t)row * HDIM + col) =
                        __floats2bfloat162_rn(v0, v1);
                    ls0 += v0; ls1 += v1;
                    lq0 = fmaf(v0, v0, lq0); lq1 = fmaf(v1, v1, lq1);
                } else {
                    __nv_bfloat16 h0 = __float2bfloat16(v0), h1 = __float2bfloat16(v1);
                    *(__nv_bfloat162*)(ga.CH + (size_t)row * HDIM + col) =
                        __nv_bfloat162(h0, h1);
                    *(__nv_bfloat162*)(ga.CL + (size_t)row * HDIM + col) =
                        __nv_bfloat162(__float2bfloat16(v0 - __bfloat162float(h0)),
                                       __float2bfloat16(v1 - __bfloat162float(h1)));
                }
            }
        }
        if (ga.outmode == 0) {
            atomicAdd(&s_sum[lcol], ls0);     atomicAdd(&s_sum[lcol + 1], ls1);
            atomicAdd(&s_sq[lcol], lq0);      atomicAdd(&s_sq[lcol + 1], lq1);
        }
    }
    if (ga.outmode == 0) {
        __syncthreads();
        if (tid < 128) {
            atomicAdd(&ga.cs[col0 + tid], s_sum[tid]);
            atomicAdd(&ga.cs2[col0 + tid], s_sq[tid]);
        }
        // ---- last-CTA BN finalize (replaces k_bnfinal launch) ----
        __threadfence();
        if (tid == 0) {
            int ticket = atomicAdd(&g_ctr, 1);
            s_last = (ticket == GEMM_CTAS - 1) ? 1 : 0;
        }
        __syncthreads();
        if (s_last) {
            int j = tid;   // 256 threads = HDIM
            const float invN = 1.0f / (float)N_NODES;
            float mu = ga.cs[j] * invN;
            float var = ga.cs2[j] * invN - mu * mu;
            float sc = ga.gamma[j] * rsqrtf(var + EPS);
            ga.scale[j] = sc;
            ga.shift[j] = ga.beta[j] - mu * sc;
        }
    }
}

// ============ norm: h_new = relu(raw*scale+shift) + hh ; 16B vectorized ======
__global__ void __launch_bounds__(256) k_norm(
    const __nv_bfloat16* __restrict__ RAW, const float* __restrict__ scale,
    const float* __restrict__ shift, __nv_bfloat16* __restrict__ HH)
{
    size_t i = (size_t)blockIdx.x * 256 + threadIdx.x;   // over N*H/8 uint4s
    int j = (int)((i & 31) << 3);
    uint4 rw = ((const uint4*)RAW)[i];
    uint4 hw = ((const uint4*)HH)[i];
    const uint32_t* rwp = &rw.x;
    const uint32_t* hwp = &hw.x;
    uint32_t ow[4];
#pragma unroll
    for (int t = 0; t < 4; t++) {
        float2 rv = __bfloat1622float2(*(const __nv_bfloat162*)&rwp[t]);
        float2 fh = __bfloat1622float2(*(const __nv_bfloat162*)&hwp[t]);
        float2 sc = *(const float2*)(scale + j + 2 * t);
        float2 sh = *(const float2*)(shift + j + 2 * t);
        float o0 = fmaxf(fmaf(rv.x, sc.x, sh.x), 0.f) + fh.x;
        float o1 = fmaxf(fmaf(rv.y, sc.y, sh.y), 0.f) + fh.y;
        __nv_bfloat162 o = __floats2bfloat162_rn(o0, o1);
        ow[t] = *(uint32_t*)&o;
    }
    ((uint4*)HH)[i] = make_uint4(ow[0], ow[1], ow[2], ow[3]);
}

// ============================ pooling + head =================================
__device__ __forceinline__ int lower_bound_batch(const void* batch, long long val, int is64) {
    int lo = 0, hi = N_NODES;
    while (lo < hi) {
        int mid = (lo + hi) >> 1;
        long long b = is64 ? ((const long long*)batch)[mid]
                           : (long long)((const int*)batch)[mid];
        if (b < val) lo = mid + 1; else hi = mid;
    }
    return lo;
}
// 256 threads/graph: 2 row-strides x 128 col-pairs, smem combine
__global__ void k_pool(const __nv_bfloat16* __restrict__ HH,
                       const void* __restrict__ batch, float* __restrict__ pool) {
    int g = blockIdx.x;
    __shared__ int slo, shi;
    __shared__ float s0s[128], s1s[128];
    if (threadIdx.x == 0) {
        int is64 = g_is64;
        slo = lower_bound_batch(batch, g, is64);
        shi = lower_bound_batch(batch, g + 1, is64);
    }
    __syncthreads();
    int j = threadIdx.x & 127;
    int half = threadIdx.x >> 7;
    float s0 = 0.f, s1 = 0.f;
    for (int n = slo + half; n < shi; n += 2) {
        float2 fh = __bfloat1622float2(((const __nv_bfloat162*)HH)[(size_t)n * (HDIM / 2) + j]);
        s0 += fh.x; s1 += fh.y;
    }
    if (half) { s0s[j] = s0; s1s[j] = s1; }
    __syncthreads();
    if (!half) {
        float inv = 1.0f / (float)max(shi - slo, 1);
        pool[g * HDIM + 2 * j]     = (s0 + s0s[j]) * inv;
        pool[g * HDIM + 2 * j + 1] = (s1 + s1s[j]) * inv;
    }
}
__global__ void k_final(const float* __restrict__ pool, const float* __restrict__ linW,
                        const float* __restrict__ linb, float* __restrict__ out) {
    int g = blockIdx.x * 8 + (threadIdx.x >> 5);
    int lane = threadIdx.x & 31;
    if (g >= N_GRAPHS) return;
    float s = 0.f;
#pragma unroll
    for (int q = 0; q < 8; q++) {
        int k = lane + q * 32;
        s = fmaf(pool[g * HDIM + k], linW[k], s);
    }
#pragma unroll
    for (int o = 16; o > 0; o >>= 1) s += __shfl_xor_sync(0xFFFFFFFFu, s, o);
    if (lane == 0) out[g] = s + linb[0];
}

// ============================ host orchestration ============================
extern "C" void kernel_launch(void* const* d_in, const int* in_sizes, int n_in,
                              void* d_out, int out_size) {
    const float* x   = (const float*)d_in[0];
    const void*  ei  = d_in[1];
    const void*  bat = d_in[2];
    const float* W[4][5];
    for (int b = 0; b < 4; b++)
        for (int k = 0; k < 5; k++)
            W[b][k] = (const float*)d_in[3 + b * 5 + k];
    const float* resW = (const float*)d_in[23];
    const float* resb = (const float*)d_in[24];
    const float* linW = (const float*)d_in[25];
    const float* linb = (const float*)d_in[26];
    float* out = (float*)d_out;

    void* p;
    cudaGetSymbolAddress(&p, g_h2);     __nv_bfloat16* h2b = (__nv_bfloat16*)p;
    cudaGetSymbolAddress(&p, g_hh);     __nv_bfloat16* hh = (__nv_bfloat16*)p;
    cudaGetSymbolAddress(&p, g_hl);     __nv_bfloat16* hl = (__nv_bfloat16*)p;
    cudaGetSymbolAddress(&p, g_aggh);   __nv_bfloat16* aggh = (__nv_bfloat16*)p;
    cudaGetSymbolAddress(&p, g_xh);     __nv_bfloat16* xh = (__nv_bfloat16*)p;
    cudaGetSymbolAddress(&p, g_bth);    __nv_bfloat16* bth = (__nv_bfloat16*)p;
    cudaGetSymbolAddress(&p, g_btl);    __nv_bfloat16* btl = (__nv_bfloat16*)p;
    cudaGetSymbolAddress(&p, g_deg);    int* deg = (int*)p;
    cudaGetSymbolAddress(&p, g_deginv); float* deginv = (float*)p;
    cudaGetSymbolAddress(&p, g_rowptr); int* rowptr = (int*)p;
    cudaGetSymbolAddress(&p, g_cursor); int* cursor = (int*)p;
    cudaGetSymbolAddress(&p, g_csr);    int* csr = (int*)p;
    cudaGetSymbolAddress(&p, g_blksum); int* blksum = (int*)p;
    cudaGetSymbolAddress(&p, g_blkoff); int* blkoff = (int*)p;
    cudaGetSymbolAddress(&p, g_colsum);   float* colsum = (float*)p;
    cudaGetSymbolAddress(&p, g_colsumsq); float* colsumsq = (float*)p;
    cudaGetSymbolAddress(&p, g_scale);  float* scale = (float*)p;
    cudaGetSymbolAddress(&p, g_shift);  float* shift = (float*)p;
    cudaGetSymbolAddress(&p, g_pool);   float* pool = (float*)p;

    static cudaStream_t s1 = nullptr;
    static cudaEvent_t evFork = nullptr, evXh = nullptr, evSide = nullptr;
    if (!s1) {
        cudaStreamCreateWithFlags(&s1, cudaStreamNonBlocking);
        cudaEventCreateWithFlags(&evFork, cudaEventDisableTiming);
        cudaEventCreateWithFlags(&evXh, cudaEventDisableTiming);
        cudaEventCreateWithFlags(&evSide, cudaEventDisableTiming);
        cudaFuncSetAttribute(k_mma<true>, cudaFuncAttributeMaxDynamicSharedMemorySize, SMEM_MMA);
        cudaFuncSetAttribute(k_mma<false>, cudaFuncAttributeMaxDynamicSharedMemorySize, SMEM_MMA);
    }

    auto bt_h = [&](int slot) { return bth + (size_t)slot * HDIM * HDIM; };
    auto bt_l = [&](int slot) { return btl + (size_t)slot * HDIM * HDIM; };

    const int agg_blocks = (N_NODES * 32 + 255) / 256;
    const dim3 gemm_grid((N_NODES + 127) / 128, HDIM / 128);
    const int norm_grid = (N_NODES * HDIM / 8 + 255) / 256;

    // ---- fork: CSR chain on stream 0, prep chain + res-GEMM on s1 ----
    cudaEventRecord(evFork, 0);
    cudaStreamWaitEvent(s1, evFork, 0);

    // stream 0: CSR build
    k_prep0<<<(N_NODES + 255) / 256, 256>>>((const int*)ei);
    k_degree<<<(N_EDGES / 2 + 255) / 256, 256>>>(ei, deg);
    k_scan_partial<<<NB, SB>>>(deg, blksum);
    k_scan_blk<<<1, 32>>>(blksum, blkoff, rowptr);
    k_scan_final<<<NB, SB>>>(deg, blkoff, rowptr, deginv);
    k_fillcsr<<<(N_EDGES / 2 + 255) / 256, 256>>>(ei, rowptr, cursor, csr);

    // stream s1: operand prep + residual GEMM
    k_split_x<<<(N_NODES * F_IN / 4 + 255) / 256, 256, 0, s1>>>((const float4*)x, xh);
    cudaEventRecord(evXh, s1);
    {
        PrepJobs j;
        j.W[0] = W[0][0]; j.K[0] = F_IN; j.OH[0] = bt_h(0); j.OL[0] = bt_l(0);
        j.W[1] = W[0][2]; j.K[1] = F_IN; j.OH[1] = bt_h(1); j.OL[1] = bt_l(1);
        j.W[2] = resW;    j.K[2] = F_IN; j.OH[2] = bt_h(2); j.OL[2] = bt_l(2);
        for (int b = 1; b < 4; b++) {
            int s0 = 3 + (b - 1) * 2;
            j.W[s0] = W[b][0]; j.K[s0] = HDIM; j.OH[s0] = bt_h(s0); j.OL[s0] = bt_l(s0);
            j.W[s0 + 1] = W[b][2]; j.K[s0 + 1] = HDIM; j.OH[s0 + 1] = bt_h(s0 + 1); j.OL[s0 + 1] = bt_l(s0 + 1);
        }
        k_prep_w_all<<<dim3(HDIM, 9), 256, 0, s1>>>(j);
    }
    {   // residual GEMM: (x @ resW + resb) -> hh/hl split (keeps weight-lo)
        GArgs a = {};
        a.pr[0] = { xh, bt_h(2), bt_l(2) };
        a.npair = 1; a.K = F_IN; a.bias = resb;
        a.CH = hh; a.CL = hl; a.outmode = 1;
        k_mma<true><<<gemm_grid, 256, SMEM_MMA, s1>>>(a);
    }
    cudaEventRecord(evSide, s1);

    // stream 0: layer-1 aggregation — overlaps res-GEMM
    cudaStreamWaitEvent(0, evXh, 0);
    k_agg<F_IN><<<agg_blocks, 256>>>(xh, rowptr, csr, deginv, aggh);
    cudaStreamWaitEvent(0, evSide, 0);

    // ---- block 1 ----
    {
        GArgs a = {};
        a.pr[0] = { aggh, bt_h(0), nullptr };
        a.pr[1] = { xh,   bt_h(1), nullptr };
        a.npair = 2; a.K = F_IN; a.bias = W[0][1];
        a.C = h2b; a.cs = colsum; a.cs2 = colsumsq; a.outmode = 0;
        a.gamma = W[0][3]; a.beta = W[0][4]; a.scale = scale; a.shift = shift;
        k_mma<false><<<gemm_grid, 256, SMEM_MMA>>>(a);
    }
    k_norm<<<norm_grid, 256>>>(h2b, scale, shift, hh);

    // ---- blocks 2..4 ----
    for (int b = 1; b < 4; b++) {
        int sl = 3 + (b - 1) * 2, sr = sl + 1;
        k_agg<HDIM><<<agg_blocks, 256>>>(hh, rowptr, csr, deginv, aggh);
        GArgs a = {};
        a.pr[0] = { aggh, bt_h(sl), nullptr };
        a.pr[1] = { hh,   bt_h(sr), nullptr };
        a.npair = 2; a.K = HDIM; a.bias = W[b][1];
        a.C = h2b; a.cs = colsum; a.cs2 = colsumsq; a.outmode = 0;
        a.gamma = W[b][3]; a.beta = W[b][4]; a.scale = scale; a.shift = shift;
        k_mma<false><<<gemm_grid, 256, SMEM_MMA>>>(a);
        k_norm<<<norm_grid, 256>>>(h2b, scale, shift, hh);
    }

    // ---- pooling + head ----
    k_pool<<<N_GRAPHS, 256>>>(hh, bat, pool);
    k_final<<<N_GRAPHS / 8, 256>>>(pool, linW, linb, out);
}